// round 14
// baseline (speedup 1.0000x reference)
#include <cuda_runtime.h>
#include <cuda_fp16.h>
#include <math.h>
#include <stdint.h>

// ---------------- problem constants ----------------
#define NN 32
#define CC 3
#define NP 14
#define PS 16
#define DD 768
#define HH 12
#define DH 64
#define SS 197
#define LL 8
#define FF 3072
#define OUTC 1000
#define NPATCH (NP*NP)    // 196
#define ROWS (NN*SS)      // 6304
#define PROWS (NN*NPATCH) // 6272

#define FLAG_BIAS 1
#define FLAG_GELU 2
#define FLAG_RES  4
#define FLAG_HALF_OUT 8

// ---------------- scratch (device globals; no runtime allocation) ----------------
__device__ float g_x[ROWS * DD];
__device__ float g_h[ROWS * DD];
__device__ float g_lpart[4 * NN * OUTC];

__device__ __half g_patch_f16[PROWS * DD];
__device__ __half g_h_f16[ROWS * DD];
__device__ __half g_u_f16[ROWS * FF];
__device__ __half g_Wm_f16[DD * DD];
__device__ __half g_W1_f16[LL * DD * FF];
__device__ __half g_W2_f16[LL * FF * DD];

__device__ __forceinline__ float gelu_exact(float x) {
    return 0.5f * x * (1.0f + erff(x * 0.70710678118654752f));
}

// ---------------- fp32 -> fp16 conversion ----------------
__global__ void conv_f16(const float* __restrict__ src, __half* __restrict__ dst, int n) {
    int i = (blockIdx.x * blockDim.x + threadIdx.x) * 4;
    if (i >= n) return;
    float4 v = *(const float4*)&src[i];
    __half2* d = (__half2*)&dst[i];
    d[0] = __floats2half2_rn(v.x, v.y);
    d[1] = __floats2half2_rn(v.z, v.w);
}

// ---------------- patch extraction (writes fp16) ----------------
__global__ void extract_patches(const float* __restrict__ images,
                                __half* __restrict__ P) {
    int idx = blockIdx.x * blockDim.x + threadIdx.x;
    if (idx >= PROWS * DD) return;
    int row = idx / DD;
    int col = idx - row * DD;
    int n = row / NPATCH;
    int p = row - n * NPATCH;
    int py = p / NP, px = p - py * NP;
    int c = col / (PS * PS);
    int r = col - c * PS * PS;
    int i = r / PS, j = r - i * PS;
    int H = NP * PS;
    float v = images[(((size_t)n * CC + c) * H + (py * PS + i)) * H + (px * PS + j)];
    P[idx] = __float2half(v);
}

// ---------------- assemble tokens + cls + pos ----------------
__global__ void assemble(const float* __restrict__ tok, const float* __restrict__ cls,
                         const float* __restrict__ pos, float* __restrict__ x) {
    int idx = blockIdx.x * blockDim.x + threadIdx.x;
    if (idx >= ROWS * DD) return;
    int row = idx / DD;
    int d = idx - row * DD;
    int n = row / SS;
    int s = row - n * SS;
    float v;
    if (s == 0) v = cls[d];
    else        v = tok[((size_t)n * NPATCH + (s - 1)) * DD + d];
    x[idx] = v + pos[(size_t)s * DD + d];
}

// ---------------- warp-per-row layernorm -> fp16 out (no barriers) ----------------
__global__ __launch_bounds__(256) void ln_warp(const float* __restrict__ x,
                                               const float* __restrict__ w,
                                               const float* __restrict__ b,
                                               __half* __restrict__ oh) {
    int warp = threadIdx.x >> 5, lane = threadIdx.x & 31;
    int row = blockIdx.x * 8 + warp;
    const float* xr = x + (size_t)row * DD;

    float4 v[6];
    float s = 0.f;
    #pragma unroll
    for (int i = 0; i < 6; i++) {
        v[i] = *(const float4*)&xr[(lane + 32 * i) * 4];
        s += v[i].x + v[i].y + v[i].z + v[i].w;
    }
    #pragma unroll
    for (int o = 16; o; o >>= 1) s += __shfl_xor_sync(0xffffffffu, s, o);
    float mean = s * (1.0f / DD);

    float sq = 0.f;
    #pragma unroll
    for (int i = 0; i < 6; i++) {
        v[i].x -= mean; v[i].y -= mean; v[i].z -= mean; v[i].w -= mean;
        sq += v[i].x * v[i].x + v[i].y * v[i].y + v[i].z * v[i].z + v[i].w * v[i].w;
    }
    #pragma unroll
    for (int o = 16; o; o >>= 1) sq += __shfl_xor_sync(0xffffffffu, sq, o);
    float rstd = rsqrtf(sq * (1.0f / DD) + 1e-5f);

    __half* orow = oh + (size_t)row * DD;
    #pragma unroll
    for (int i = 0; i < 6; i++) {
        int c = (lane + 32 * i) * 4;
        float4 wv = *(const float4*)&w[c];
        float4 bv = *(const float4*)&b[c];
        float r0 = v[i].x * rstd * wv.x + bv.x;
        float r1 = v[i].y * rstd * wv.y + bv.y;
        float r2 = v[i].z * rstd * wv.z + bv.z;
        float r3 = v[i].w * rstd * wv.w + bv.w;
        __half2 h01 = __floats2half2_rn(r0, r1);
        __half2 h23 = __floats2half2_rn(r2, r3);
        uint2 pk;
        pk.x = *(uint32_t*)&h01;
        pk.y = *(uint32_t*)&h23;
        *(uint2*)&orow[c] = pk;
    }
}

// ================= fp16 tensor-core GEMM, templated tile width ==========
#define BM 128
#define BKK 32
#define ASTR 40
#define ASZ (BM*ASTR)
#define NSTAGE 3

__device__ __forceinline__ void ldsm_x4(uint32_t addr, uint32_t* r) {
    asm volatile("ldmatrix.sync.aligned.m8n8.x4.shared.b16 {%0,%1,%2,%3}, [%4];\n"
                 : "=r"(r[0]), "=r"(r[1]), "=r"(r[2]), "=r"(r[3]) : "r"(addr));
}
__device__ __forceinline__ void ldsm_x4_t(uint32_t addr, uint32_t* r) {
    asm volatile("ldmatrix.sync.aligned.m8n8.x4.trans.shared.b16 {%0,%1,%2,%3}, [%4];\n"
                 : "=r"(r[0]), "=r"(r[1]), "=r"(r[2]), "=r"(r[3]) : "r"(addr));
}
__device__ __forceinline__ void mma_f16(float* c, const uint32_t* a, const uint32_t* b) {
    asm volatile("mma.sync.aligned.m16n8k16.row.col.f32.f16.f16.f32 "
                 "{%0,%1,%2,%3},{%4,%5,%6,%7},{%8,%9},{%0,%1,%2,%3};\n"
                 : "+f"(c[0]), "+f"(c[1]), "+f"(c[2]), "+f"(c[3])
                 : "r"(a[0]), "r"(a[1]), "r"(a[2]), "r"(a[3]), "r"(b[0]), "r"(b[1]));
}
__device__ __forceinline__ void cpa16(uint32_t dst, const void* src, int bytes) {
    asm volatile("cp.async.cg.shared.global [%0], [%1], 16, %2;\n"
                 :: "r"(dst), "l"(src), "r"(bytes));
}
__device__ __forceinline__ void cp_commit() {
    asm volatile("cp.async.commit_group;\n");
}
__device__ __forceinline__ void cp_wait1() {
    asm volatile("cp.async.wait_group 1;\n");
}

template <int BN_T, int BSTR_T>
__device__ __forceinline__ void gemm_issue_stage_t(
    uint32_t smem_u32, int stage,
    const __half* __restrict__ A, int lda,
    const __half* __restrict__ B, int ldb,
    int M, int m0, int n0, int kb, int tid)
{
    constexpr int BSZ_T = BKK * BSTR_T;
    constexpr int STAGE_BYTES_T = (ASZ + BSZ_T) * 2;
    constexpr int BCHUNK_ROW = BN_T / 8;                    // 16B chunks per B row
    constexpr int BCH = (BKK * BCHUNK_ROW) / 256;           // chunks per thread
    uint32_t s = smem_u32 + (uint32_t)stage * STAGE_BYTES_T;
    uint32_t sA = s;
    uint32_t sB = s + ASZ * 2;
    #pragma unroll
    for (int i = 0; i < 2; i++) {
        int chunk = tid + 256 * i;
        int row = chunk >> 2;
        int c16 = chunk & 3;
        int gr = m0 + row;
        int bytes = (gr < M) ? 16 : 0;
        size_t goff = (size_t)gr * lda + kb + c16 * 8;
        uint32_t doff = (uint32_t)(row * ASTR + c16 * 8) * 2;
        cpa16(sA + doff, A + goff, bytes);
    }
    #pragma unroll
    for (int i = 0; i < BCH; i++) {
        int chunk = tid + 256 * i;
        int row = chunk / BCHUNK_ROW;
        int c16 = chunk % BCHUNK_ROW;
        size_t goff = (size_t)(kb + row) * ldb + n0 + c16 * 8;
        uint32_t doff = (uint32_t)(row * BSTR_T + c16 * 8) * 2;
        cpa16(sB + doff, B + goff, 16);
    }
}

template <int BN_T, int BSTR_T, int NI_T>
__global__ __launch_bounds__(256, 2) void gemm_f16_tpl(
    const __half* __restrict__ A, int lda,
    const __half* __restrict__ B, int ldb,
    float* __restrict__ C, __half* __restrict__ Ch,
    int ldc, const float* __restrict__ bias,
    int M, int N, int K, int flags)
{
    constexpr int BSZ_T = BKK * BSTR_T;
    constexpr int STAGE_BYTES_T = (ASZ + BSZ_T) * 2;
    extern __shared__ __half smbuf[];
    int tid = threadIdx.x;
    int m0 = blockIdx.y * BM;
    int n0 = blockIdx.x * BN_T;
    int warp = tid >> 5;
    int lane = tid & 31;
    int wm = (warp >> 2) * 64;
    int wn = (warp & 3) * (BN_T / 4);

    float acc[4][NI_T][4];
    #pragma unroll
    for (int i = 0; i < 4; i++)
        #pragma unroll
        for (int j = 0; j < NI_T; j++)
            #pragma unroll
            for (int c = 0; c < 4; c++) acc[i][j][c] = 0.f;

    uint32_t smem_u32 = (uint32_t)__cvta_generic_to_shared(smbuf);
    const int nk = K / BKK;

    gemm_issue_stage_t<BN_T, BSTR_T>(smem_u32, 0, A, lda, B, ldb, M, m0, n0, 0, tid);
    cp_commit();
    gemm_issue_stage_t<BN_T, BSTR_T>(smem_u32, 1, A, lda, B, ldb, M, m0, n0, BKK, tid);
    cp_commit();

    int st = 0;
    for (int kt = 0; kt < nk; kt++) {
        cp_wait1();
        __syncthreads();

        int nxt = kt + 2;
        if (nxt < nk) {
            int nst = st + 2;
            if (nst >= NSTAGE) nst -= NSTAGE;
            gemm_issue_stage_t<BN_T, BSTR_T>(smem_u32, nst, A, lda, B, ldb, M, m0, n0, nxt * BKK, tid);
        }
        cp_commit();

        uint32_t s = smem_u32 + (uint32_t)st * STAGE_BYTES_T;
        uint32_t a_base = s;
        uint32_t b_base = s + ASZ * 2;

        #pragma unroll
        for (int ks = 0; ks < 2; ks++) {
            int kc = ks * 16;
            uint32_t bf[NI_T][2];
            int brow = kc + ((lane >> 3) & 1) * 8 + (lane & 7);
            #pragma unroll
            for (int j = 0; j < NI_T / 2; j++) {
                int bcol = wn + j * 16 + (lane >> 4) * 8;
                uint32_t off = (uint32_t)((brow * BSTR_T + bcol) * 2);
                uint32_t th[4];
                ldsm_x4_t(b_base + off, th);
                bf[2 * j][0] = th[0];
                bf[2 * j][1] = th[1];
                bf[2 * j + 1][0] = th[2];
                bf[2 * j + 1][1] = th[3];
            }
            int arow = lane & 15;
            int acol = kc + (lane >> 4) * 8;
            #pragma unroll
            for (int mi = 0; mi < 4; mi++) {
                uint32_t af[4];
                uint32_t off = (uint32_t)(((wm + mi * 16 + arow) * ASTR + acol) * 2);
                ldsm_x4(a_base + off, af);
                #pragma unroll
                for (int ni = 0; ni < NI_T; ni++) {
                    mma_f16(acc[mi][ni], af, bf[ni]);
                }
            }
        }

        st = (st + 1 == NSTAGE) ? 0 : st + 1;
    }

    // ---- epilogue ----
    #pragma unroll
    for (int mi = 0; mi < 4; mi++) {
        int r0 = m0 + wm + mi * 16 + (lane >> 2);
        #pragma unroll
        for (int ni = 0; ni < NI_T; ni++) {
            int c0 = n0 + wn + ni * 8 + (lane & 3) * 2;
            #pragma unroll
            for (int half = 0; half < 2; half++) {
                int r = r0 + half * 8;
                if (r >= M) continue;
                #pragma unroll
                for (int e = 0; e < 2; e++) {
                    int c = c0 + e;
                    float val = acc[mi][ni][half * 2 + e];
                    if (flags & FLAG_BIAS) val += bias[c];
                    if (flags & FLAG_GELU) val = gelu_exact(val);
                    if (flags & FLAG_HALF_OUT) {
                        Ch[(size_t)r * ldc + c] = __float2half(val);
                    } else {
                        float* p = &C[(size_t)r * ldc + c];
                        if (flags & FLAG_RES) *p += val; else *p = val;
                    }
                }
            }
        }
    }
}

#define GEMM_SMEM_128 (NSTAGE * (ASZ + BKK * 136) * 2)   // 56832
#define GEMM_SMEM_64  (NSTAGE * (ASZ + BKK * 72) * 2)    // 44544

// ================= fused QKV + attention: block per (n, head), 13 warps ==========
#define AT_ROWS 208
#define AT_STR 72
#define HS_ELEMS (AT_ROWS * AT_STR)          // 14976
#define WS_ELEMS (3 * 64 * AT_STR)           // 13824
#define FUSED_SMEM_BYTES ((2 * HS_ELEMS + WS_ELEMS + HS_ELEMS) * 2)   // 117504
#define FW_THREADS 416

__global__ __launch_bounds__(FW_THREADS, 1) void qkv_attn_fused(
    const __half* __restrict__ hbuf,
    const float* __restrict__ Wq, const float* __restrict__ Wk, const float* __restrict__ Wv,
    const float* __restrict__ bq, const float* __restrict__ bk, const float* __restrict__ bv,
    float* __restrict__ x)
{
    extern __shared__ __half fsm[];
    __half* Hs = fsm;
    __half* Ws = Hs + HS_ELEMS;
    __half* Ks = Ws + WS_ELEMS;
    __half* Vs = Ks + HS_ELEMS;

    int nh = blockIdx.x;
    int n = nh / HH, h = nh - n * HH;
    int tid = threadIdx.x;
    int warp = tid >> 5, lane = tid & 31;

    #pragma unroll
    for (int i = 0; i < 4; i++) {
        int idx = tid + i * FW_THREADS;
        int t = idx >> 3;
        int c8 = (idx & 7) * 8;
        uint4 hv = make_uint4(0, 0, 0, 0);
        if (t < SS) hv = *(const uint4*)(hbuf + ((size_t)(n * SS + t)) * DD + h * DH + c8);
        *(uint4*)(Hs + t * AT_STR + c8) = hv;
    }
    const float* wsrc[3] = {Wq + h * DH * DH, Wk + h * DH * DH, Wv + h * DH * DH};
    for (int idx = tid; idx < 3 * DH * DH; idx += FW_THREADS) {
        int mat = idx >> 12;
        int rem = idx & 4095;
        int d = rem >> 6, e = rem & 63;
        Ws[mat * 64 * AT_STR + d * AT_STR + e] = __float2half(wsrc[mat][d * 64 + e]);
    }
    __syncthreads();

    uint32_t h_base = (uint32_t)__cvta_generic_to_shared(Hs);
    uint32_t w_base = (uint32_t)__cvta_generic_to_shared(Ws);
    uint32_t k_base = (uint32_t)__cvta_generic_to_shared(Ks);
    uint32_t v_base = (uint32_t)__cvta_generic_to_shared(Vs);

    int s0 = warp * 16;

    float acc[3][8][4];
    #pragma unroll
    for (int m = 0; m < 3; m++)
        #pragma unroll
        for (int j = 0; j < 8; j++) {
            acc[m][j][0] = 0.f; acc[m][j][1] = 0.f;
            acc[m][j][2] = 0.f; acc[m][j][3] = 0.f;
        }

    #pragma unroll
    for (int ks = 0; ks < 4; ks++) {
        int kc = ks * 16;
        uint32_t af[4];
        uint32_t aoff = (uint32_t)(((s0 + (lane & 15)) * AT_STR + kc + (lane >> 4) * 8) * 2);
        ldsm_x4(h_base + aoff, af);
        int brow = kc + ((lane >> 3) & 1) * 8 + (lane & 7);
        #pragma unroll
        for (int mat = 0; mat < 3; mat++) {
            #pragma unroll
            for (int j = 0; j < 4; j++) {
                int bcol = j * 16 + (lane >> 4) * 8;
                uint32_t th[4];
                ldsm_x4_t(w_base + (uint32_t)((mat * 64 * AT_STR + brow * AT_STR + bcol) * 2), th);
                mma_f16(acc[mat][2 * j],     af, th);
                mma_f16(acc[mat][2 * j + 1], af, th + 2);
            }
        }
    }

    const float* bq_h = bq + h * DH;
    uint32_t qa[4][4];
    #pragma unroll
    for (int ks = 0; ks < 4; ks++) {
        int colA = 16 * ks + (lane & 3) * 2;
        int colB = colA + 8;
        float b0 = bq_h[colA], b1 = bq_h[colA + 1];
        float b2 = bq_h[colB], b3 = bq_h[colB + 1];
        __half2 t0 = __floats2half2_rn(acc[0][2 * ks][0] + b0, acc[0][2 * ks][1] + b1);
        __half2 t1 = __floats2half2_rn(acc[0][2 * ks][2] + b0, acc[0][2 * ks][3] + b1);
        __half2 t2 = __floats2half2_rn(acc[0][2 * ks + 1][0] + b2, acc[0][2 * ks + 1][1] + b3);
        __half2 t3 = __floats2half2_rn(acc[0][2 * ks + 1][2] + b2, acc[0][2 * ks + 1][3] + b3);
        qa[ks][0] = *(uint32_t*)&t0;
        qa[ks][1] = *(uint32_t*)&t1;
        qa[ks][2] = *(uint32_t*)&t2;
        qa[ks][3] = *(uint32_t*)&t3;
    }

    {
        const float* bk_h = bk + h * DH;
        const float* bv_h = bv + h * DH;
        #pragma unroll
        for (int half = 0; half < 2; half++) {
            int r = s0 + (lane >> 2) + half * 8;
            __half* krow = Ks + r * AT_STR;
            __half* vrow = Vs + r * AT_STR;
            #pragma unroll
            for (int nj = 0; nj < 8; nj++) {
                int col = nj * 8 + (lane & 3) * 2;
                __half2 kv = __floats2half2_rn(acc[1][nj][half * 2]     + bk_h[col],
                                               acc[1][nj][half * 2 + 1] + bk_h[col + 1]);
                __half2 vv = __floats2half2_rn(acc[2][nj][half * 2]     + bv_h[col],
                                               acc[2][nj][half * 2 + 1] + bv_h[col + 1]);
                *(__half2*)&krow[col] = kv;
                *(__half2*)&vrow[col] = vv;
            }
        }
    }
    __syncthreads();

    const float scale = 0.125f;
    float c[26][4];
    #pragma unroll
    for (int j = 0; j < 26; j++) {
        c[j][0] = 0.f; c[j][1] = 0.f; c[j][2] = 0.f; c[j][3] = 0.f;
    }
    #pragma unroll
    for (int ks = 0; ks < 4; ks++) {
        int ncol = ks * 16 + ((lane >> 3) & 1) * 8;
        #pragma unroll
        for (int j = 0; j < 13; j++) {
            uint32_t b[4];
            int nrow = j * 16 + (lane >> 4) * 8 + (lane & 7);
            ldsm_x4(k_base + (uint32_t)((nrow * AT_STR + ncol) * 2), b);
            mma_f16(c[2 * j],     qa[ks], b);
            mma_f16(c[2 * j + 1], qa[ks], b + 2);
        }
    }

    float mx0 = -1e30f, mx1 = -1e30f;
    #pragma unroll
    for (int j = 0; j < 26; j++) {
        int tcol = j * 8 + (lane & 3) * 2;
        #pragma unroll
        for (int e = 0; e < 2; e++) {
            float s0v = c[j][e] * scale;
            float s1v = c[j][2 + e] * scale;
            if (tcol + e >= SS) { s0v = -1e30f; s1v = -1e30f; }
            c[j][e] = s0v;
            c[j][2 + e] = s1v;
            mx0 = fmaxf(mx0, s0v);
            mx1 = fmaxf(mx1, s1v);
        }
    }
    mx0 = fmaxf(mx0, __shfl_xor_sync(0xffffffffu, mx0, 1));
    mx0 = fmaxf(mx0, __shfl_xor_sync(0xffffffffu, mx0, 2));
    mx1 = fmaxf(mx1, __shfl_xor_sync(0xffffffffu, mx1, 1));
    mx1 = fmaxf(mx1, __shfl_xor_sync(0xffffffffu, mx1, 2));

    float sum0 = 0.f, sum1 = 0.f;
    #pragma unroll
    for (int j = 0; j < 26; j++) {
        #pragma unroll
        for (int e = 0; e < 2; e++) {
            float p0 = __expf(c[j][e] - mx0);
            float p1 = __expf(c[j][2 + e] - mx1);
            c[j][e] = p0;
            c[j][2 + e] = p1;
            sum0 += p0;
            sum1 += p1;
        }
    }
    sum0 += __shfl_xor_sync(0xffffffffu, sum0, 1);
    sum0 += __shfl_xor_sync(0xffffffffu, sum0, 2);
    sum1 += __shfl_xor_sync(0xffffffffu, sum1, 1);
    sum1 += __shfl_xor_sync(0xffffffffu, sum1, 2);
    float inv0 = 1.0f / sum0;
    float inv1 = 1.0f / sum1;

    float o[8][4];
    #pragma unroll
    for (int j = 0; j < 8; j++) {
        o[j][0] = 0.f; o[j][1] = 0.f; o[j][2] = 0.f; o[j][3] = 0.f;
    }
    #pragma unroll
    for (int j = 0; j < 13; j++) {
        uint32_t a[4];
        __half2 h0 = __floats2half2_rn(c[2 * j][0] * inv0, c[2 * j][1] * inv0);
        __half2 h1 = __floats2half2_rn(c[2 * j][2] * inv1, c[2 * j][3] * inv1);
        __half2 h2 = __floats2half2_rn(c[2 * j + 1][0] * inv0, c[2 * j + 1][1] * inv0);
        __half2 h3 = __floats2half2_rn(c[2 * j + 1][2] * inv1, c[2 * j + 1][3] * inv1);
        a[0] = *(uint32_t*)&h0;
        a[1] = *(uint32_t*)&h1;
        a[2] = *(uint32_t*)&h2;
        a[3] = *(uint32_t*)&h3;
        int brow = j * 16 + ((lane >> 3) & 1) * 8 + (lane & 7);
        #pragma unroll
        for (int nj = 0; nj < 4; nj++) {
            uint32_t b[4];
            int bcol = nj * 16 + (lane >> 4) * 8;
            ldsm_x4_t(v_base + (uint32_t)((brow * AT_STR + bcol) * 2), b);
            mma_f16(o[2 * nj],     a, b);
            mma_f16(o[2 * nj + 1], a, b + 2);
        }
    }

    int rloc = lane >> 2;
    #pragma unroll
    for (int half = 0; half < 2; half++) {
        int srow = s0 + rloc + half * 8;
        if (srow >= SS) continue;
        float* xr = x + ((size_t)(n * SS + srow)) * DD + h * DH;
        #pragma unroll
        for (int nj = 0; nj < 8; nj++) {
            int col = nj * 8 + (lane & 3) * 2;
            xr[col]     += o[nj][half * 2];
            xr[col + 1] += o[nj][half * 2 + 1];
        }
    }
}

// ---------------- split-K classification head: grid (16 n-tiles, 4 k-chunks) -------
__global__ __launch_bounds__(256) void head_gemm(const float* __restrict__ x,
                                                 const float* __restrict__ Wout,
                                                 float* __restrict__ part) {
    __shared__ float As[16][34];
    __shared__ float Bs[16][68];
    int tid = threadIdx.x;
    int n0 = blockIdx.x * 64;
    int kz = blockIdx.y;
    int tx = tid & 15, ty = tid >> 4;

    float acc[2][4];
    acc[0][0] = 0.f; acc[0][1] = 0.f; acc[0][2] = 0.f; acc[0][3] = 0.f;
    acc[1][0] = 0.f; acc[1][1] = 0.f; acc[1][2] = 0.f; acc[1][3] = 0.f;

    for (int k0 = kz * 192; k0 < kz * 192 + 192; k0 += 16) {
        if (tid < 128) {
            int arow = tid >> 2;
            int akcol = (tid & 3) * 4;
            float4 a4 = *(const float4*)&x[(size_t)arow * (SS * DD) + k0 + akcol];
            As[akcol + 0][arow] = a4.x;
            As[akcol + 1][arow] = a4.y;
            As[akcol + 2][arow] = a4.z;
            As[akcol + 3][arow] = a4.w;
        }
        {
            int brow = tid >> 4;
            int bcol = (tid & 15) * 4;
            int gn = n0 + bcol;
            const float* Brow = &Wout[(size_t)(k0 + brow) * OUTC];
            float4 b4;
            b4.x = (gn + 0 < OUTC) ? Brow[gn + 0] : 0.f;
            b4.y = (gn + 1 < OUTC) ? Brow[gn + 1] : 0.f;
            b4.z = (gn + 2 < OUTC) ? Brow[gn + 2] : 0.f;
            b4.w = (gn + 3 < OUTC) ? Brow[gn + 3] : 0.f;
            *(float4*)&Bs[brow][bcol] = b4;
        }
        __syncthreads();

        #pragma unroll
        for (int kk = 0; kk < 16; kk++) {
            float a0 = As[kk][ty * 2];
            float a1 = As[kk][ty * 2 + 1];
            float4 b4 = *(float4*)&Bs[kk][tx * 4];
            acc[0][0] += a0 * b4.x; acc[0][1] += a0 * b4.y;
            acc[0][2] += a0 * b4.z; acc[0][3] += a0 * b4.w;
            acc[1][0] += a1 * b4.x; acc[1][1] += a1 * b4.y;
            acc[1][2] += a1 * b4.z; acc[1][3] += a1 * b4.w;
        }
        __syncthreads();
    }

    float* pbase = part + (size_t)kz * NN * OUTC;
    #pragma unroll
    for (int i = 0; i < 2; i++) {
        int r = ty * 2 + i;
        #pragma unroll
        for (int j = 0; j < 4; j++) {
            int cidx = n0 + tx * 4 + j;
            if (cidx < OUTC) pbase[(size_t)r * OUTC + cidx] = acc[i][j];
        }
    }
}

// ---------------- final softmax (sums 4 K-partials + bias) ----------------
__global__ __launch_bounds__(256) void softmax_out(const float* __restrict__ part,
                                                   const float* __restrict__ bout,
                                                   float* __restrict__ out) {
    __shared__ float sl[OUTC];
    __shared__ float sh[8];
    int n = blockIdx.x;
    int tid = threadIdx.x;
    int lane = tid & 31, wp = tid >> 5;

    for (int cidx = tid; cidx < OUTC; cidx += 256) {
        size_t o = (size_t)n * OUTC + cidx;
        sl[cidx] = bout[cidx] + part[o] + part[NN * OUTC + o] +
                   part[2 * NN * OUTC + o] + part[3 * NN * OUTC + o];
    }
    __syncthreads();

    float mx = -1e30f;
    for (int cidx = tid; cidx < OUTC; cidx += 256) mx = fmaxf(mx, sl[cidx]);
    #pragma unroll
    for (int o = 16; o; o >>= 1) mx = fmaxf(mx, __shfl_xor_sync(0xffffffffu, mx, o));
    if (lane == 0) sh[wp] = mx;
    __syncthreads();
    float gmx = sh[0];
    #pragma unroll
    for (int i = 1; i < 8; i++) gmx = fmaxf(gmx, sh[i]);
    __syncthreads();

    float sum = 0.f;
    for (int cidx = tid; cidx < OUTC; cidx += 256) sum += __expf(sl[cidx] - gmx);
    #pragma unroll
    for (int o = 16; o; o >>= 1) sum += __shfl_xor_sync(0xffffffffu, sum, o);
    if (lane == 0) sh[wp] = sum;
    __syncthreads();
    float tot = 0.f;
    #pragma unroll
    for (int i = 0; i < 8; i++) tot += sh[i];
    float inv = 1.0f / tot;

    for (int cidx = tid; cidx < OUTC; cidx += 256)
        out[(size_t)n * OUTC + cidx] = __expf(sl[cidx] - gmx) * inv;
}

// ---------------- launch ----------------
extern "C" void kernel_launch(void* const* d_in, const int* in_sizes, int n_in,
                              void* d_out, int out_size) {
    const float* images = (const float*)d_in[0];
    const float* Wm     = (const float*)d_in[1];
    const float* bm     = (const float*)d_in[2];
    const float* cls    = (const float*)d_in[3];
    const float* pos    = (const float*)d_in[4];
    const float* ln1w   = (const float*)d_in[5];
    const float* ln1b   = (const float*)d_in[6];
    const float* Wq     = (const float*)d_in[7];
    const float* bq     = (const float*)d_in[8];
    const float* Wk     = (const float*)d_in[9];
    const float* bk     = (const float*)d_in[10];
    const float* Wv     = (const float*)d_in[11];
    const float* bv     = (const float*)d_in[12];
    const float* ln2w   = (const float*)d_in[13];
    const float* ln2b   = (const float*)d_in[14];
    const float* W1     = (const float*)d_in[15];
    const float* b1     = (const float*)d_in[16];
    const float* W2     = (const float*)d_in[17];
    const float* b2     = (const float*)d_in[18];
    const float* Wout   = (const float*)d_in[19];
    const float* bout   = (const float*)d_in[20];
    float* out = (float*)d_out;

    float *p_x, *p_h, *p_lpart;
    cudaGetSymbolAddress((void**)&p_x, g_x);
    cudaGetSymbolAddress((void**)&p_h, g_h);
    cudaGetSymbolAddress((void**)&p_lpart, g_lpart);

    __half *p_patch, *p_hh, *p_u, *p_Wm, *p_W1, *p_W2;
    cudaGetSymbolAddress((void**)&p_patch, g_patch_f16);
    cudaGetSymbolAddress((void**)&p_hh, g_h_f16);
    cudaGetSymbolAddress((void**)&p_u, g_u_f16);
    cudaGetSymbolAddress((void**)&p_Wm, g_Wm_f16);
    cudaGetSymbolAddress((void**)&p_W1, g_W1_f16);
    cudaGetSymbolAddress((void**)&p_W2, g_W2_f16);

    cudaFuncSetAttribute(qkv_attn_fused, cudaFuncAttributeMaxDynamicSharedMemorySize, FUSED_SMEM_BYTES);
    cudaFuncSetAttribute((const void*)gemm_f16_tpl<128, 136, 4>,
                         cudaFuncAttributeMaxDynamicSharedMemorySize, GEMM_SMEM_128);
    cudaFuncSetAttribute((const void*)gemm_f16_tpl<64, 72, 2>,
                         cudaFuncAttributeMaxDynamicSharedMemorySize, GEMM_SMEM_64);

    // ---- one-time weight conversions ----
    conv_f16<<<(DD * DD / 4 + 255) / 256, 256>>>(Wm, p_Wm, DD * DD);
    conv_f16<<<(LL * DD * FF / 4 + 255) / 256, 256>>>(W1, p_W1, LL * DD * FF);
    conv_f16<<<(LL * FF * DD / 4 + 255) / 256, 256>>>(W2, p_W2, LL * FF * DD);

    // ---- patch extraction + embed GEMM (294 blocks: single wave) ----
    extract_patches<<<(PROWS * DD + 255) / 256, 256>>>(images, p_patch);
    gemm_f16_tpl<128, 136, 4><<<dim3(DD / 128, (PROWS + 127) / 128), 256, GEMM_SMEM_128>>>(
        p_patch, DD, p_Wm, DD,
        p_h, nullptr, DD, bm, PROWS, DD, DD, FLAG_BIAS);
    assemble<<<(ROWS * DD + 255) / 256, 256>>>(p_h, cls, pos, p_x);

    for (int l = 0; l < LL; l++) {
        ln_warp<<<ROWS / 8, 256>>>(p_x, ln1w + l * DD, ln1b + l * DD, p_hh);

        qkv_attn_fused<<<NN * HH, FW_THREADS, FUSED_SMEM_BYTES>>>(
            p_hh,
            Wq + (size_t)l * HH * DH * DH, Wk + (size_t)l * HH * DH * DH, Wv + (size_t)l * HH * DH * DH,
            bq + (size_t)l * DD, bk + (size_t)l * DD, bv + (size_t)l * DD,
            p_x);

        ln_warp<<<ROWS / 8, 256>>>(p_x, ln2w + l * DD, ln2b + l * DD, p_hh);

        // MLP1: 24x50 = 1200 blocks (4.05 waves, ~1% tail)
        gemm_f16_tpl<128, 136, 4><<<dim3(FF / 128, (ROWS + 127) / 128), 256, GEMM_SMEM_128>>>(
            p_hh, DD,
            p_W1 + (size_t)l * DD * FF, FF,
            nullptr, p_u, FF, b1 + (size_t)l * FF,
            ROWS, FF, DD, FLAG_BIAS | FLAG_GELU | FLAG_HALF_OUT);

        // MLP2: BN=64 -> 12x50 = 600 blocks (2.03 waves, ~3% tail vs old 48%)
        gemm_f16_tpl<64, 72, 2><<<dim3(DD / 64, (ROWS + 127) / 128), 256, GEMM_SMEM_64>>>(
            p_u, FF,
            p_W2 + (size_t)l * FF * DD, DD,
            p_x, nullptr, DD, b2 + (size_t)l * DD,
            ROWS, DD, FF, FLAG_BIAS | FLAG_RES);
    }

    // classification head: split-K partials (deterministic), bias+reduce in softmax
    head_gemm<<<dim3(16, 4), 256>>>(p_x, Wout, p_lpart);
    softmax_out<<<NN, 256>>>(p_lpart, bout, out);
}

// round 15
// speedup vs baseline: 1.1129x; 1.1129x over previous
#include <cuda_runtime.h>
#include <cuda_fp16.h>
#include <math.h>
#include <stdint.h>

// ---------------- problem constants ----------------
#define NN 32
#define CC 3
#define NP 14
#define PS 16
#define DD 768
#define HH 12
#define DH 64
#define SS 197
#define LL 8
#define FF 3072
#define OUTC 1000
#define NPATCH (NP*NP)    // 196
#define ROWS (NN*SS)      // 6304
#define PROWS (NN*NPATCH) // 6272

#define FLAG_BIAS 1
#define FLAG_GELU 2
#define FLAG_RES  4
#define FLAG_HALF_OUT 8

// ---------------- scratch (device globals; no runtime allocation) ----------------
__device__ float g_x[ROWS * DD];
__device__ float g_scratch[2 * ROWS * DD];   // embed output + MLP2 split-K partials
__device__ float g_lpart[4 * NN * OUTC];

__device__ __half g_patch_f16[PROWS * DD];
__device__ __half g_h_f16[ROWS * DD];
__device__ __half g_u_f16[ROWS * FF];
__device__ __half g_Wm_f16[DD * DD];
__device__ __half g_W1_f16[LL * DD * FF];
__device__ __half g_W2_f16[LL * FF * DD];

__device__ __forceinline__ float gelu_exact(float x) {
    return 0.5f * x * (1.0f + erff(x * 0.70710678118654752f));
}

// ---------------- fp32 -> fp16 conversion ----------------
__global__ void conv_f16(const float* __restrict__ src, __half* __restrict__ dst, int n) {
    int i = (blockIdx.x * blockDim.x + threadIdx.x) * 4;
    if (i >= n) return;
    float4 v = *(const float4*)&src[i];
    __half2* d = (__half2*)&dst[i];
    d[0] = __floats2half2_rn(v.x, v.y);
    d[1] = __floats2half2_rn(v.z, v.w);
}

// ---------------- patch extraction (writes fp16) ----------------
__global__ void extract_patches(const float* __restrict__ images,
                                __half* __restrict__ P) {
    int idx = blockIdx.x * blockDim.x + threadIdx.x;
    if (idx >= PROWS * DD) return;
    int row = idx / DD;
    int col = idx - row * DD;
    int n = row / NPATCH;
    int p = row - n * NPATCH;
    int py = p / NP, px = p - py * NP;
    int c = col / (PS * PS);
    int r = col - c * PS * PS;
    int i = r / PS, j = r - i * PS;
    int H = NP * PS;
    float v = images[(((size_t)n * CC + c) * H + (py * PS + i)) * H + (px * PS + j)];
    P[idx] = __float2half(v);
}

// ---------------- assemble tokens + cls + pos ----------------
__global__ void assemble(const float* __restrict__ tok, const float* __restrict__ cls,
                         const float* __restrict__ pos, float* __restrict__ x) {
    int idx = blockIdx.x * blockDim.x + threadIdx.x;
    if (idx >= ROWS * DD) return;
    int row = idx / DD;
    int d = idx - row * DD;
    int n = row / SS;
    int s = row - n * SS;
    float v;
    if (s == 0) v = cls[d];
    else        v = tok[((size_t)n * NPATCH + (s - 1)) * DD + d];
    x[idx] = v + pos[(size_t)s * DD + d];
}

// ---------------- warp-per-row layernorm -> fp16 out (no barriers) ----------------
__global__ __launch_bounds__(256) void ln_warp(const float* __restrict__ x,
                                               const float* __restrict__ w,
                                               const float* __restrict__ b,
                                               __half* __restrict__ oh) {
    int warp = threadIdx.x >> 5, lane = threadIdx.x & 31;
    int row = blockIdx.x * 8 + warp;
    const float* xr = x + (size_t)row * DD;

    float4 v[6];
    float s = 0.f;
    #pragma unroll
    for (int i = 0; i < 6; i++) {
        v[i] = *(const float4*)&xr[(lane + 32 * i) * 4];
        s += v[i].x + v[i].y + v[i].z + v[i].w;
    }
    #pragma unroll
    for (int o = 16; o; o >>= 1) s += __shfl_xor_sync(0xffffffffu, s, o);
    float mean = s * (1.0f / DD);

    float sq = 0.f;
    #pragma unroll
    for (int i = 0; i < 6; i++) {
        v[i].x -= mean; v[i].y -= mean; v[i].z -= mean; v[i].w -= mean;
        sq += v[i].x * v[i].x + v[i].y * v[i].y + v[i].z * v[i].z + v[i].w * v[i].w;
    }
    #pragma unroll
    for (int o = 16; o; o >>= 1) sq += __shfl_xor_sync(0xffffffffu, sq, o);
    float rstd = rsqrtf(sq * (1.0f / DD) + 1e-5f);

    __half* orow = oh + (size_t)row * DD;
    #pragma unroll
    for (int i = 0; i < 6; i++) {
        int c = (lane + 32 * i) * 4;
        float4 wv = *(const float4*)&w[c];
        float4 bv = *(const float4*)&b[c];
        float r0 = v[i].x * rstd * wv.x + bv.x;
        float r1 = v[i].y * rstd * wv.y + bv.y;
        float r2 = v[i].z * rstd * wv.z + bv.z;
        float r3 = v[i].w * rstd * wv.w + bv.w;
        __half2 h01 = __floats2half2_rn(r0, r1);
        __half2 h23 = __floats2half2_rn(r2, r3);
        uint2 pk;
        pk.x = *(uint32_t*)&h01;
        pk.y = *(uint32_t*)&h23;
        *(uint2*)&orow[c] = pk;
    }
}

// ================= fp16 tensor-core GEMM (128x128 tile, optional split-K) ==========
#define BM 128
#define BN 128
#define BKK 32
#define ASTR 40
#define BSTR 136
#define ASZ (BM*ASTR)
#define BSZ (BKK*BSTR)
#define STAGE_ELEMS (ASZ + BSZ)
#define STAGE_BYTES (STAGE_ELEMS*2)
#define NSTAGE 3
#define GEMM_SMEM_BYTES (NSTAGE * STAGE_BYTES)

__device__ __forceinline__ void ldsm_x4(uint32_t addr, uint32_t* r) {
    asm volatile("ldmatrix.sync.aligned.m8n8.x4.shared.b16 {%0,%1,%2,%3}, [%4];\n"
                 : "=r"(r[0]), "=r"(r[1]), "=r"(r[2]), "=r"(r[3]) : "r"(addr));
}
__device__ __forceinline__ void ldsm_x4_t(uint32_t addr, uint32_t* r) {
    asm volatile("ldmatrix.sync.aligned.m8n8.x4.trans.shared.b16 {%0,%1,%2,%3}, [%4];\n"
                 : "=r"(r[0]), "=r"(r[1]), "=r"(r[2]), "=r"(r[3]) : "r"(addr));
}
__device__ __forceinline__ void mma_f16(float* c, const uint32_t* a, const uint32_t* b) {
    asm volatile("mma.sync.aligned.m16n8k16.row.col.f32.f16.f16.f32 "
                 "{%0,%1,%2,%3},{%4,%5,%6,%7},{%8,%9},{%0,%1,%2,%3};\n"
                 : "+f"(c[0]), "+f"(c[1]), "+f"(c[2]), "+f"(c[3])
                 : "r"(a[0]), "r"(a[1]), "r"(a[2]), "r"(a[3]), "r"(b[0]), "r"(b[1]));
}
__device__ __forceinline__ void cpa16(uint32_t dst, const void* src, int bytes) {
    asm volatile("cp.async.cg.shared.global [%0], [%1], 16, %2;\n"
                 :: "r"(dst), "l"(src), "r"(bytes));
}
__device__ __forceinline__ void cp_commit() {
    asm volatile("cp.async.commit_group;\n");
}
__device__ __forceinline__ void cp_wait1() {
    asm volatile("cp.async.wait_group 1;\n");
}

__device__ __forceinline__ void gemm_issue_stage(
    uint32_t smem_u32, int stage,
    const __half* __restrict__ A, int lda,
    const __half* __restrict__ B, int ldb,
    int M, int m0, int n0, int kb, int tid)
{
    uint32_t s = smem_u32 + (uint32_t)stage * STAGE_BYTES;
    uint32_t sA = s;
    uint32_t sB = s + ASZ * 2;
    #pragma unroll
    for (int i = 0; i < 2; i++) {
        int chunk = tid + 256 * i;
        int row = chunk >> 2;
        int c16 = chunk & 3;
        int gr = m0 + row;
        int bytes = (gr < M) ? 16 : 0;
        size_t goff = (size_t)gr * lda + kb + c16 * 8;
        uint32_t doff = (uint32_t)(row * ASTR + c16 * 8) * 2;
        cpa16(sA + doff, A + goff, bytes);
    }
    #pragma unroll
    for (int i = 0; i < 2; i++) {
        int chunk = tid + 256 * i;
        int row = chunk >> 4;
        int c16 = chunk & 15;
        size_t goff = (size_t)(kb + row) * ldb + n0 + c16 * 8;
        uint32_t doff = (uint32_t)(row * BSTR + c16 * 8) * 2;
        cpa16(sB + doff, B + goff, 16);
    }
}

__global__ __launch_bounds__(256, 2) void gemm_f16(
    const __half* __restrict__ A, int lda,
    const __half* __restrict__ B, int ldb,
    float* __restrict__ C, __half* __restrict__ Ch,
    int ldc, const float* __restrict__ bias,
    int M, int N, int K, int flags)
{
    extern __shared__ __half smbuf[];
    int tid = threadIdx.x;
    int m0 = blockIdx.y * BM;
    int n0 = blockIdx.x * BN;
    // split-K: z-slice shifts operands; C goes to partial buffer slice kz
    int kz = blockIdx.z;
    if (kz) {
        A += (size_t)kz * K;
        B += (size_t)kz * K * (size_t)ldb;
        C += (size_t)kz * (size_t)M * (size_t)ldc;
    }
    int warp = tid >> 5;
    int lane = tid & 31;
    int wm = (warp >> 2) * 64;
    int wn = (warp & 3) * 32;

    float acc[4][4][4];
    #pragma unroll
    for (int i = 0; i < 4; i++)
        #pragma unroll
        for (int j = 0; j < 4; j++)
            #pragma unroll
            for (int c = 0; c < 4; c++) acc[i][j][c] = 0.f;

    uint32_t smem_u32 = (uint32_t)__cvta_generic_to_shared(smbuf);
    const int nk = K / BKK;

    gemm_issue_stage(smem_u32, 0, A, lda, B, ldb, M, m0, n0, 0, tid);
    cp_commit();
    gemm_issue_stage(smem_u32, 1, A, lda, B, ldb, M, m0, n0, BKK, tid);
    cp_commit();

    int st = 0;
    for (int kt = 0; kt < nk; kt++) {
        cp_wait1();
        __syncthreads();

        int nxt = kt + 2;
        if (nxt < nk) {
            int nst = st + 2;
            if (nst >= NSTAGE) nst -= NSTAGE;
            gemm_issue_stage(smem_u32, nst, A, lda, B, ldb, M, m0, n0, nxt * BKK, tid);
        }
        cp_commit();

        uint32_t s = smem_u32 + (uint32_t)st * STAGE_BYTES;
        uint32_t a_base = s;
        uint32_t b_base = s + ASZ * 2;

        #pragma unroll
        for (int ks = 0; ks < 2; ks++) {
            int kc = ks * 16;
            uint32_t bf[4][2];
            int brow = kc + ((lane >> 3) & 1) * 8 + (lane & 7);
            #pragma unroll
            for (int j = 0; j < 2; j++) {
                int bcol = wn + j * 16 + (lane >> 4) * 8;
                uint32_t off = (uint32_t)((brow * BSTR + bcol) * 2);
                uint32_t th[4];
                ldsm_x4_t(b_base + off, th);
                bf[2 * j][0] = th[0];
                bf[2 * j][1] = th[1];
                bf[2 * j + 1][0] = th[2];
                bf[2 * j + 1][1] = th[3];
            }
            int arow = lane & 15;
            int acol = kc + (lane >> 4) * 8;
            #pragma unroll
            for (int mi = 0; mi < 4; mi++) {
                uint32_t af[4];
                uint32_t off = (uint32_t)(((wm + mi * 16 + arow) * ASTR + acol) * 2);
                ldsm_x4(a_base + off, af);
                #pragma unroll
                for (int ni = 0; ni < 4; ni++) {
                    mma_f16(acc[mi][ni], af, bf[ni]);
                }
            }
        }

        st = (st + 1 == NSTAGE) ? 0 : st + 1;
    }

    // ---- epilogue ----
    #pragma unroll
    for (int mi = 0; mi < 4; mi++) {
        int r0 = m0 + wm + mi * 16 + (lane >> 2);
        #pragma unroll
        for (int ni = 0; ni < 4; ni++) {
            int c0 = n0 + wn + ni * 8 + (lane & 3) * 2;
            #pragma unroll
            for (int half = 0; half < 2; half++) {
                int r = r0 + half * 8;
                if (r >= M) continue;
                #pragma unroll
                for (int e = 0; e < 2; e++) {
                    int c = c0 + e;
                    float val = acc[mi][ni][half * 2 + e];
                    if (flags & FLAG_BIAS) val += bias[c];
                    if (flags & FLAG_GELU) val = gelu_exact(val);
                    if (flags & FLAG_HALF_OUT) {
                        Ch[(size_t)r * ldc + c] = __float2half(val);
                    } else {
                        float* p = &C[(size_t)r * ldc + c];
                        if (flags & FLAG_RES) *p += val; else *p = val;
                    }
                }
            }
        }
    }
}

// ---------------- split-K reduce for MLP2: x += p0 + p1 + b2 ----------------
__global__ __launch_bounds__(256) void mlp2_reduce(const float* __restrict__ part,
                                                   const float* __restrict__ b2,
                                                   float* __restrict__ x) {
    int i = (blockIdx.x * blockDim.x + threadIdx.x) * 4;
    if (i >= ROWS * DD) return;
    int col = i % DD;
    float4 a = *(const float4*)&part[i];
    float4 b = *(const float4*)&part[ROWS * DD + i];
    float4 bi = *(const float4*)&b2[col];
    float4 xv = *(float4*)&x[i];
    xv.x += a.x + b.x + bi.x;
    xv.y += a.y + b.y + bi.y;
    xv.z += a.z + b.z + bi.z;
    xv.w += a.w + b.w + bi.w;
    *(float4*)&x[i] = xv;
}

// ================= fused QKV + attention: block per (n, head), 13 warps ==========
#define AT_ROWS 208
#define AT_STR 72
#define HS_ELEMS (AT_ROWS * AT_STR)          // 14976
#define WS_ELEMS (3 * 64 * AT_STR)           // 13824
#define FUSED_SMEM_BYTES ((2 * HS_ELEMS + WS_ELEMS + HS_ELEMS) * 2)   // 117504
#define FW_THREADS 416

__global__ __launch_bounds__(FW_THREADS, 1) void qkv_attn_fused(
    const __half* __restrict__ hbuf,
    const float* __restrict__ Wq, const float* __restrict__ Wk, const float* __restrict__ Wv,
    const float* __restrict__ bq, const float* __restrict__ bk, const float* __restrict__ bv,
    float* __restrict__ x)
{
    extern __shared__ __half fsm[];
    __half* Hs = fsm;
    __half* Ws = Hs + HS_ELEMS;
    __half* Ks = Ws + WS_ELEMS;
    __half* Vs = Ks + HS_ELEMS;

    int nh = blockIdx.x;
    int n = nh / HH, h = nh - n * HH;
    int tid = threadIdx.x;
    int warp = tid >> 5, lane = tid & 31;

    #pragma unroll
    for (int i = 0; i < 4; i++) {
        int idx = tid + i * FW_THREADS;
        int t = idx >> 3;
        int c8 = (idx & 7) * 8;
        uint4 hv = make_uint4(0, 0, 0, 0);
        if (t < SS) hv = *(const uint4*)(hbuf + ((size_t)(n * SS + t)) * DD + h * DH + c8);
        *(uint4*)(Hs + t * AT_STR + c8) = hv;
    }
    const float* wsrc[3] = {Wq + h * DH * DH, Wk + h * DH * DH, Wv + h * DH * DH};
    for (int idx = tid; idx < 3 * DH * DH; idx += FW_THREADS) {
        int mat = idx >> 12;
        int rem = idx & 4095;
        int d = rem >> 6, e = rem & 63;
        Ws[mat * 64 * AT_STR + d * AT_STR + e] = __float2half(wsrc[mat][d * 64 + e]);
    }
    __syncthreads();

    uint32_t h_base = (uint32_t)__cvta_generic_to_shared(Hs);
    uint32_t w_base = (uint32_t)__cvta_generic_to_shared(Ws);
    uint32_t k_base = (uint32_t)__cvta_generic_to_shared(Ks);
    uint32_t v_base = (uint32_t)__cvta_generic_to_shared(Vs);

    int s0 = warp * 16;

    float acc[3][8][4];
    #pragma unroll
    for (int m = 0; m < 3; m++)
        #pragma unroll
        for (int j = 0; j < 8; j++) {
            acc[m][j][0] = 0.f; acc[m][j][1] = 0.f;
            acc[m][j][2] = 0.f; acc[m][j][3] = 0.f;
        }

    #pragma unroll
    for (int ks = 0; ks < 4; ks++) {
        int kc = ks * 16;
        uint32_t af[4];
        uint32_t aoff = (uint32_t)(((s0 + (lane & 15)) * AT_STR + kc + (lane >> 4) * 8) * 2);
        ldsm_x4(h_base + aoff, af);
        int brow = kc + ((lane >> 3) & 1) * 8 + (lane & 7);
        #pragma unroll
        for (int mat = 0; mat < 3; mat++) {
            #pragma unroll
            for (int j = 0; j < 4; j++) {
                int bcol = j * 16 + (lane >> 4) * 8;
                uint32_t th[4];
                ldsm_x4_t(w_base + (uint32_t)((mat * 64 * AT_STR + brow * AT_STR + bcol) * 2), th);
                mma_f16(acc[mat][2 * j],     af, th);
                mma_f16(acc[mat][2 * j + 1], af, th + 2);
            }
        }
    }

    const float* bq_h = bq + h * DH;
    uint32_t qa[4][4];
    #pragma unroll
    for (int ks = 0; ks < 4; ks++) {
        int colA = 16 * ks + (lane & 3) * 2;
        int colB = colA + 8;
        float b0 = bq_h[colA], b1 = bq_h[colA + 1];
        float b2 = bq_h[colB], b3 = bq_h[colB + 1];
        __half2 t0 = __floats2half2_rn(acc[0][2 * ks][0] + b0, acc[0][2 * ks][1] + b1);
        __half2 t1 = __floats2half2_rn(acc[0][2 * ks][2] + b0, acc[0][2 * ks][3] + b1);
        __half2 t2 = __floats2half2_rn(acc[0][2 * ks + 1][0] + b2, acc[0][2 * ks + 1][1] + b3);
        __half2 t3 = __floats2half2_rn(acc[0][2 * ks + 1][2] + b2, acc[0][2 * ks + 1][3] + b3);
        qa[ks][0] = *(uint32_t*)&t0;
        qa[ks][1] = *(uint32_t*)&t1;
        qa[ks][2] = *(uint32_t*)&t2;
        qa[ks][3] = *(uint32_t*)&t3;
    }

    {
        const float* bk_h = bk + h * DH;
        const float* bv_h = bv + h * DH;
        #pragma unroll
        for (int half = 0; half < 2; half++) {
            int r = s0 + (lane >> 2) + half * 8;
            __half* krow = Ks + r * AT_STR;
            __half* vrow = Vs + r * AT_STR;
            #pragma unroll
            for (int nj = 0; nj < 8; nj++) {
                int col = nj * 8 + (lane & 3) * 2;
                __half2 kv = __floats2half2_rn(acc[1][nj][half * 2]     + bk_h[col],
                                               acc[1][nj][half * 2 + 1] + bk_h[col + 1]);
                __half2 vv = __floats2half2_rn(acc[2][nj][half * 2]     + bv_h[col],
                                               acc[2][nj][half * 2 + 1] + bv_h[col + 1]);
                *(__half2*)&krow[col] = kv;
                *(__half2*)&vrow[col] = vv;
            }
        }
    }
    __syncthreads();

    const float scale = 0.125f;
    float c[26][4];
    #pragma unroll
    for (int j = 0; j < 26; j++) {
        c[j][0] = 0.f; c[j][1] = 0.f; c[j][2] = 0.f; c[j][3] = 0.f;
    }
    #pragma unroll
    for (int ks = 0; ks < 4; ks++) {
        int ncol = ks * 16 + ((lane >> 3) & 1) * 8;
        #pragma unroll
        for (int j = 0; j < 13; j++) {
            uint32_t b[4];
            int nrow = j * 16 + (lane >> 4) * 8 + (lane & 7);
            ldsm_x4(k_base + (uint32_t)((nrow * AT_STR + ncol) * 2), b);
            mma_f16(c[2 * j],     qa[ks], b);
            mma_f16(c[2 * j + 1], qa[ks], b + 2);
        }
    }

    float mx0 = -1e30f, mx1 = -1e30f;
    #pragma unroll
    for (int j = 0; j < 26; j++) {
        int tcol = j * 8 + (lane & 3) * 2;
        #pragma unroll
        for (int e = 0; e < 2; e++) {
            float s0v = c[j][e] * scale;
            float s1v = c[j][2 + e] * scale;
            if (tcol + e >= SS) { s0v = -1e30f; s1v = -1e30f; }
            c[j][e] = s0v;
            c[j][2 + e] = s1v;
            mx0 = fmaxf(mx0, s0v);
            mx1 = fmaxf(mx1, s1v);
        }
    }
    mx0 = fmaxf(mx0, __shfl_xor_sync(0xffffffffu, mx0, 1));
    mx0 = fmaxf(mx0, __shfl_xor_sync(0xffffffffu, mx0, 2));
    mx1 = fmaxf(mx1, __shfl_xor_sync(0xffffffffu, mx1, 1));
    mx1 = fmaxf(mx1, __shfl_xor_sync(0xffffffffu, mx1, 2));

    float sum0 = 0.f, sum1 = 0.f;
    #pragma unroll
    for (int j = 0; j < 26; j++) {
        #pragma unroll
        for (int e = 0; e < 2; e++) {
            float p0 = __expf(c[j][e] - mx0);
            float p1 = __expf(c[j][2 + e] - mx1);
            c[j][e] = p0;
            c[j][2 + e] = p1;
            sum0 += p0;
            sum1 += p1;
        }
    }
    sum0 += __shfl_xor_sync(0xffffffffu, sum0, 1);
    sum0 += __shfl_xor_sync(0xffffffffu, sum0, 2);
    sum1 += __shfl_xor_sync(0xffffffffu, sum1, 1);
    sum1 += __shfl_xor_sync(0xffffffffu, sum1, 2);
    float inv0 = 1.0f / sum0;
    float inv1 = 1.0f / sum1;

    float o[8][4];
    #pragma unroll
    for (int j = 0; j < 8; j++) {
        o[j][0] = 0.f; o[j][1] = 0.f; o[j][2] = 0.f; o[j][3] = 0.f;
    }
    #pragma unroll
    for (int j = 0; j < 13; j++) {
        uint32_t a[4];
        __half2 h0 = __floats2half2_rn(c[2 * j][0] * inv0, c[2 * j][1] * inv0);
        __half2 h1 = __floats2half2_rn(c[2 * j][2] * inv1, c[2 * j][3] * inv1);
        __half2 h2 = __floats2half2_rn(c[2 * j + 1][0] * inv0, c[2 * j + 1][1] * inv0);
        __half2 h3 = __floats2half2_rn(c[2 * j + 1][2] * inv1, c[2 * j + 1][3] * inv1);
        a[0] = *(uint32_t*)&h0;
        a[1] = *(uint32_t*)&h1;
        a[2] = *(uint32_t*)&h2;
        a[3] = *(uint32_t*)&h3;
        int brow = j * 16 + ((lane >> 3) & 1) * 8 + (lane & 7);
        #pragma unroll
        for (int nj = 0; nj < 4; nj++) {
            uint32_t b[4];
            int bcol = nj * 16 + (lane >> 4) * 8;
            ldsm_x4_t(v_base + (uint32_t)((brow * AT_STR + bcol) * 2), b);
            mma_f16(o[2 * nj],     a, b);
            mma_f16(o[2 * nj + 1], a, b + 2);
        }
    }

    int rloc = lane >> 2;
    #pragma unroll
    for (int half = 0; half < 2; half++) {
        int srow = s0 + rloc + half * 8;
        if (srow >= SS) continue;
        float* xr = x + ((size_t)(n * SS + srow)) * DD + h * DH;
        #pragma unroll
        for (int nj = 0; nj < 8; nj++) {
            int col = nj * 8 + (lane & 3) * 2;
            xr[col]     += o[nj][half * 2];
            xr[col + 1] += o[nj][half * 2 + 1];
        }
    }
}

// ---------------- split-K classification head: grid (16 n-tiles, 4 k-chunks) -------
__global__ __launch_bounds__(256) void head_gemm(const float* __restrict__ x,
                                                 const float* __restrict__ Wout,
                                                 float* __restrict__ part) {
    __shared__ float As[16][34];
    __shared__ float Bs[16][68];
    int tid = threadIdx.x;
    int n0 = blockIdx.x * 64;
    int kz = blockIdx.y;
    int tx = tid & 15, ty = tid >> 4;

    float acc[2][4];
    acc[0][0] = 0.f; acc[0][1] = 0.f; acc[0][2] = 0.f; acc[0][3] = 0.f;
    acc[1][0] = 0.f; acc[1][1] = 0.f; acc[1][2] = 0.f; acc[1][3] = 0.f;

    for (int k0 = kz * 192; k0 < kz * 192 + 192; k0 += 16) {
        if (tid < 128) {
            int arow = tid >> 2;
            int akcol = (tid & 3) * 4;
            float4 a4 = *(const float4*)&x[(size_t)arow * (SS * DD) + k0 + akcol];
            As[akcol + 0][arow] = a4.x;
            As[akcol + 1][arow] = a4.y;
            As[akcol + 2][arow] = a4.z;
            As[akcol + 3][arow] = a4.w;
        }
        {
            int brow = tid >> 4;
            int bcol = (tid & 15) * 4;
            int gn = n0 + bcol;
            const float* Brow = &Wout[(size_t)(k0 + brow) * OUTC];
            float4 b4;
            b4.x = (gn + 0 < OUTC) ? Brow[gn + 0] : 0.f;
            b4.y = (gn + 1 < OUTC) ? Brow[gn + 1] : 0.f;
            b4.z = (gn + 2 < OUTC) ? Brow[gn + 2] : 0.f;
            b4.w = (gn + 3 < OUTC) ? Brow[gn + 3] : 0.f;
            *(float4*)&Bs[brow][bcol] = b4;
        }
        __syncthreads();

        #pragma unroll
        for (int kk = 0; kk < 16; kk++) {
            float a0 = As[kk][ty * 2];
            float a1 = As[kk][ty * 2 + 1];
            float4 b4 = *(float4*)&Bs[kk][tx * 4];
            acc[0][0] += a0 * b4.x; acc[0][1] += a0 * b4.y;
            acc[0][2] += a0 * b4.z; acc[0][3] += a0 * b4.w;
            acc[1][0] += a1 * b4.x; acc[1][1] += a1 * b4.y;
            acc[1][2] += a1 * b4.z; acc[1][3] += a1 * b4.w;
        }
        __syncthreads();
    }

    float* pbase = part + (size_t)kz * NN * OUTC;
    #pragma unroll
    for (int i = 0; i < 2; i++) {
        int r = ty * 2 + i;
        #pragma unroll
        for (int j = 0; j < 4; j++) {
            int cidx = n0 + tx * 4 + j;
            if (cidx < OUTC) pbase[(size_t)r * OUTC + cidx] = acc[i][j];
        }
    }
}

// ---------------- final softmax (sums 4 K-partials + bias) ----------------
__global__ __launch_bounds__(256) void softmax_out(const float* __restrict__ part,
                                                   const float* __restrict__ bout,
                                                   float* __restrict__ out) {
    __shared__ float sl[OUTC];
    __shared__ float sh[8];
    int n = blockIdx.x;
    int tid = threadIdx.x;
    int lane = tid & 31, wp = tid >> 5;

    for (int cidx = tid; cidx < OUTC; cidx += 256) {
        size_t o = (size_t)n * OUTC + cidx;
        sl[cidx] = bout[cidx] + part[o] + part[NN * OUTC + o] +
                   part[2 * NN * OUTC + o] + part[3 * NN * OUTC + o];
    }
    __syncthreads();

    float mx = -1e30f;
    for (int cidx = tid; cidx < OUTC; cidx += 256) mx = fmaxf(mx, sl[cidx]);
    #pragma unroll
    for (int o = 16; o; o >>= 1) mx = fmaxf(mx, __shfl_xor_sync(0xffffffffu, mx, o));
    if (lane == 0) sh[wp] = mx;
    __syncthreads();
    float gmx = sh[0];
    #pragma unroll
    for (int i = 1; i < 8; i++) gmx = fmaxf(gmx, sh[i]);
    __syncthreads();

    float sum = 0.f;
    for (int cidx = tid; cidx < OUTC; cidx += 256) sum += __expf(sl[cidx] - gmx);
    #pragma unroll
    for (int o = 16; o; o >>= 1) sum += __shfl_xor_sync(0xffffffffu, sum, o);
    if (lane == 0) sh[wp] = sum;
    __syncthreads();
    float tot = 0.f;
    #pragma unroll
    for (int i = 0; i < 8; i++) tot += sh[i];
    float inv = 1.0f / tot;

    for (int cidx = tid; cidx < OUTC; cidx += 256)
        out[(size_t)n * OUTC + cidx] = __expf(sl[cidx] - gmx) * inv;
}

// ---------------- launch ----------------
extern "C" void kernel_launch(void* const* d_in, const int* in_sizes, int n_in,
                              void* d_out, int out_size) {
    const float* images = (const float*)d_in[0];
    const float* Wm     = (const float*)d_in[1];
    const float* bm     = (const float*)d_in[2];
    const float* cls    = (const float*)d_in[3];
    const float* pos    = (const float*)d_in[4];
    const float* ln1w   = (const float*)d_in[5];
    const float* ln1b   = (const float*)d_in[6];
    const float* Wq     = (const float*)d_in[7];
    const float* bq     = (const float*)d_in[8];
    const float* Wk     = (const float*)d_in[9];
    const float* bk     = (const float*)d_in[10];
    const float* Wv     = (const float*)d_in[11];
    const float* bv     = (const float*)d_in[12];
    const float* ln2w   = (const float*)d_in[13];
    const float* ln2b   = (const float*)d_in[14];
    const float* W1     = (const float*)d_in[15];
    const float* b1     = (const float*)d_in[16];
    const float* W2     = (const float*)d_in[17];
    const float* b2     = (const float*)d_in[18];
    const float* Wout   = (const float*)d_in[19];
    const float* bout   = (const float*)d_in[20];
    float* out = (float*)d_out;

    float *p_x, *p_scr, *p_lpart;
    cudaGetSymbolAddress((void**)&p_x, g_x);
    cudaGetSymbolAddress((void**)&p_scr, g_scratch);
    cudaGetSymbolAddress((void**)&p_lpart, g_lpart);

    __half *p_patch, *p_hh, *p_u, *p_Wm, *p_W1, *p_W2;
    cudaGetSymbolAddress((void**)&p_patch, g_patch_f16);
    cudaGetSymbolAddress((void**)&p_hh, g_h_f16);
    cudaGetSymbolAddress((void**)&p_u, g_u_f16);
    cudaGetSymbolAddress((void**)&p_Wm, g_Wm_f16);
    cudaGetSymbolAddress((void**)&p_W1, g_W1_f16);
    cudaGetSymbolAddress((void**)&p_W2, g_W2_f16);

    cudaFuncSetAttribute(qkv_attn_fused, cudaFuncAttributeMaxDynamicSharedMemorySize, FUSED_SMEM_BYTES);
    cudaFuncSetAttribute(gemm_f16, cudaFuncAttributeMaxDynamicSharedMemorySize, GEMM_SMEM_BYTES);

    // ---- one-time weight conversions ----
    conv_f16<<<(DD * DD / 4 + 255) / 256, 256>>>(Wm, p_Wm, DD * DD);
    conv_f16<<<(LL * DD * FF / 4 + 255) / 256, 256>>>(W1, p_W1, LL * DD * FF);
    conv_f16<<<(LL * FF * DD / 4 + 255) / 256, 256>>>(W2, p_W2, LL * FF * DD);

    // ---- patch extraction + embed GEMM (294 blocks: single wave) ----
    extract_patches<<<(PROWS * DD + 255) / 256, 256>>>(images, p_patch);
    gemm_f16<<<dim3(DD / 128, (PROWS + 127) / 128), 256, GEMM_SMEM_BYTES>>>(
        p_patch, DD, p_Wm, DD,
        p_scr, nullptr, DD, bm, PROWS, DD, DD, FLAG_BIAS);
    assemble<<<(ROWS * DD + 255) / 256, 256>>>(p_scr, cls, pos, p_x);

    for (int l = 0; l < LL; l++) {
        ln_warp<<<ROWS / 8, 256>>>(p_x, ln1w + l * DD, ln1b + l * DD, p_hh);

        qkv_attn_fused<<<NN * HH, FW_THREADS, FUSED_SMEM_BYTES>>>(
            p_hh,
            Wq + (size_t)l * HH * DH * DH, Wk + (size_t)l * HH * DH * DH, Wv + (size_t)l * HH * DH * DH,
            bq + (size_t)l * DD, bk + (size_t)l * DD, bv + (size_t)l * DD,
            p_x);

        ln_warp<<<ROWS / 8, 256>>>(p_x, ln2w + l * DD, ln2b + l * DD, p_hh);

        // MLP1: 24x50 = 1200 blocks (4.05 waves, ~1% tail)
        gemm_f16<<<dim3(FF / 128, (ROWS + 127) / 128), 256, GEMM_SMEM_BYTES>>>(
            p_hh, DD,
            p_W1 + (size_t)l * DD * FF, FF,
            nullptr, p_u, FF, b1 + (size_t)l * FF,
            ROWS, FF, DD, FLAG_BIAS | FLAG_GELU | FLAG_HALF_OUT);

        // MLP2: split-K 2 with full 128x128 tiles -> 600 blocks (2.03 waves)
        gemm_f16<<<dim3(DD / 128, (ROWS + 127) / 128, 2), 256, GEMM_SMEM_BYTES>>>(
            p_u, FF,
            p_W2 + (size_t)l * FF * DD, DD,
            p_scr, nullptr, DD, nullptr,
            ROWS, DD, FF / 2, 0);
        mlp2_reduce<<<(ROWS * DD / 4 + 255) / 256, 256>>>(p_scr, b2 + (size_t)l * DD, p_x);
    }

    // classification head: split-K partials (deterministic), bias+reduce in softmax
    head_gemm<<<dim3(16, 4), 256>>>(p_x, Wout, p_lpart);
    softmax_out<<<NN, 256>>>(p_lpart, bout, out);
}

// round 16
// speedup vs baseline: 1.1145x; 1.0015x over previous
#include <cuda_runtime.h>
#include <cuda_fp16.h>
#include <math.h>
#include <stdint.h>

// ---------------- problem constants ----------------
#define NN 32
#define CC 3
#define NP 14
#define PS 16
#define DD 768
#define HH 12
#define DH 64
#define SS 197
#define LL 8
#define FF 3072
#define OUTC 1000
#define NPATCH (NP*NP)    // 196
#define ROWS (NN*SS)      // 6304
#define PROWS (NN*NPATCH) // 6272

#define FLAG_BIAS 1
#define FLAG_GELU 2
#define FLAG_RES  4
#define FLAG_HALF_OUT 8

// ---------------- scratch (device globals; no runtime allocation) ----------------
__device__ float g_x[ROWS * DD];
__device__ float g_scratch[2 * ROWS * DD];   // embed output + MLP2 split-K partials
__device__ float g_lpart[4 * NN * OUTC];

__device__ __half g_patch_f16[PROWS * DD];
__device__ __half g_h_f16[ROWS * DD];
__device__ __half g_u_f16[ROWS * FF];
__device__ __half g_Wm_f16[DD * DD];
__device__ __half g_W1_f16[LL * DD * FF];
__device__ __half g_W2_f16[LL * FF * DD];

__device__ __forceinline__ float gelu_exact(float x) {
    return 0.5f * x * (1.0f + erff(x * 0.70710678118654752f));
}

// ---------------- fp32 -> fp16 conversion ----------------
__global__ void conv_f16(const float* __restrict__ src, __half* __restrict__ dst, int n) {
    int i = (blockIdx.x * blockDim.x + threadIdx.x) * 4;
    if (i >= n) return;
    float4 v = *(const float4*)&src[i];
    __half2* d = (__half2*)&dst[i];
    d[0] = __floats2half2_rn(v.x, v.y);
    d[1] = __floats2half2_rn(v.z, v.w);
}

// ---------------- patch extraction (writes fp16) ----------------
__global__ void extract_patches(const float* __restrict__ images,
                                __half* __restrict__ P) {
    int idx = blockIdx.x * blockDim.x + threadIdx.x;
    if (idx >= PROWS * DD) return;
    int row = idx / DD;
    int col = idx - row * DD;
    int n = row / NPATCH;
    int p = row - n * NPATCH;
    int py = p / NP, px = p - py * NP;
    int c = col / (PS * PS);
    int r = col - c * PS * PS;
    int i = r / PS, j = r - i * PS;
    int H = NP * PS;
    float v = images[(((size_t)n * CC + c) * H + (py * PS + i)) * H + (px * PS + j)];
    P[idx] = __float2half(v);
}

// ---------------- assemble tokens + cls + pos ----------------
__global__ void assemble(const float* __restrict__ tok, const float* __restrict__ cls,
                         const float* __restrict__ pos, float* __restrict__ x) {
    int idx = blockIdx.x * blockDim.x + threadIdx.x;
    if (idx >= ROWS * DD) return;
    int row = idx / DD;
    int d = idx - row * DD;
    int n = row / SS;
    int s = row - n * SS;
    float v;
    if (s == 0) v = cls[d];
    else        v = tok[((size_t)n * NPATCH + (s - 1)) * DD + d];
    x[idx] = v + pos[(size_t)s * DD + d];
}

// ---------------- warp-per-row layernorm -> fp16 out (no barriers) ----------------
__global__ __launch_bounds__(256) void ln_warp(const float* __restrict__ x,
                                               const float* __restrict__ w,
                                               const float* __restrict__ b,
                                               __half* __restrict__ oh) {
    int warp = threadIdx.x >> 5, lane = threadIdx.x & 31;
    int row = blockIdx.x * 8 + warp;
    const float* xr = x + (size_t)row * DD;

    float4 v[6];
    float s = 0.f;
    #pragma unroll
    for (int i = 0; i < 6; i++) {
        v[i] = *(const float4*)&xr[(lane + 32 * i) * 4];
        s += v[i].x + v[i].y + v[i].z + v[i].w;
    }
    #pragma unroll
    for (int o = 16; o; o >>= 1) s += __shfl_xor_sync(0xffffffffu, s, o);
    float mean = s * (1.0f / DD);

    float sq = 0.f;
    #pragma unroll
    for (int i = 0; i < 6; i++) {
        v[i].x -= mean; v[i].y -= mean; v[i].z -= mean; v[i].w -= mean;
        sq += v[i].x * v[i].x + v[i].y * v[i].y + v[i].z * v[i].z + v[i].w * v[i].w;
    }
    #pragma unroll
    for (int o = 16; o; o >>= 1) sq += __shfl_xor_sync(0xffffffffu, sq, o);
    float rstd = rsqrtf(sq * (1.0f / DD) + 1e-5f);

    __half* orow = oh + (size_t)row * DD;
    #pragma unroll
    for (int i = 0; i < 6; i++) {
        int c = (lane + 32 * i) * 4;
        float4 wv = *(const float4*)&w[c];
        float4 bv = *(const float4*)&b[c];
        float r0 = v[i].x * rstd * wv.x + bv.x;
        float r1 = v[i].y * rstd * wv.y + bv.y;
        float r2 = v[i].z * rstd * wv.z + bv.z;
        float r3 = v[i].w * rstd * wv.w + bv.w;
        __half2 h01 = __floats2half2_rn(r0, r1);
        __half2 h23 = __floats2half2_rn(r2, r3);
        uint2 pk;
        pk.x = *(uint32_t*)&h01;
        pk.y = *(uint32_t*)&h23;
        *(uint2*)&orow[c] = pk;
    }
}

// ================= fp16 tensor-core GEMM (128x128 tile, optional split-K) ==========
#define BM 128
#define BN 128
#define BKK 32
#define ASTR 40
#define BSTR 136
#define ASZ (BM*ASTR)
#define BSZ (BKK*BSTR)
#define STAGE_ELEMS (ASZ + BSZ)
#define STAGE_BYTES (STAGE_ELEMS*2)
#define NSTAGE 3
#define GEMM_SMEM_BYTES (NSTAGE * STAGE_BYTES)

__device__ __forceinline__ void ldsm_x4(uint32_t addr, uint32_t* r) {
    asm volatile("ldmatrix.sync.aligned.m8n8.x4.shared.b16 {%0,%1,%2,%3}, [%4];\n"
                 : "=r"(r[0]), "=r"(r[1]), "=r"(r[2]), "=r"(r[3]) : "r"(addr));
}
__device__ __forceinline__ void ldsm_x4_t(uint32_t addr, uint32_t* r) {
    asm volatile("ldmatrix.sync.aligned.m8n8.x4.trans.shared.b16 {%0,%1,%2,%3}, [%4];\n"
                 : "=r"(r[0]), "=r"(r[1]), "=r"(r[2]), "=r"(r[3]) : "r"(addr));
}
__device__ __forceinline__ void mma_f16(float* c, const uint32_t* a, const uint32_t* b) {
    asm volatile("mma.sync.aligned.m16n8k16.row.col.f32.f16.f16.f32 "
                 "{%0,%1,%2,%3},{%4,%5,%6,%7},{%8,%9},{%0,%1,%2,%3};\n"
                 : "+f"(c[0]), "+f"(c[1]), "+f"(c[2]), "+f"(c[3])
                 : "r"(a[0]), "r"(a[1]), "r"(a[2]), "r"(a[3]), "r"(b[0]), "r"(b[1]));
}
__device__ __forceinline__ void cpa16(uint32_t dst, const void* src, int bytes) {
    asm volatile("cp.async.cg.shared.global [%0], [%1], 16, %2;\n"
                 :: "r"(dst), "l"(src), "r"(bytes));
}
__device__ __forceinline__ void cp_commit() {
    asm volatile("cp.async.commit_group;\n");
}
__device__ __forceinline__ void cp_wait1() {
    asm volatile("cp.async.wait_group 1;\n");
}

__device__ __forceinline__ void gemm_issue_stage(
    uint32_t smem_u32, int stage,
    const __half* __restrict__ A, int lda,
    const __half* __restrict__ B, int ldb,
    int M, int m0, int n0, int kb, int tid)
{
    uint32_t s = smem_u32 + (uint32_t)stage * STAGE_BYTES;
    uint32_t sA = s;
    uint32_t sB = s + ASZ * 2;
    #pragma unroll
    for (int i = 0; i < 2; i++) {
        int chunk = tid + 256 * i;
        int row = chunk >> 2;
        int c16 = chunk & 3;
        int gr = m0 + row;
        int bytes = (gr < M) ? 16 : 0;
        size_t goff = (size_t)gr * lda + kb + c16 * 8;
        uint32_t doff = (uint32_t)(row * ASTR + c16 * 8) * 2;
        cpa16(sA + doff, A + goff, bytes);
    }
    #pragma unroll
    for (int i = 0; i < 2; i++) {
        int chunk = tid + 256 * i;
        int row = chunk >> 4;
        int c16 = chunk & 15;
        size_t goff = (size_t)(kb + row) * ldb + n0 + c16 * 8;
        uint32_t doff = (uint32_t)(row * BSTR + c16 * 8) * 2;
        cpa16(sB + doff, B + goff, 16);
    }
}

__global__ __launch_bounds__(256, 2) void gemm_f16(
    const __half* __restrict__ A, int lda,
    const __half* __restrict__ B, int ldb,
    float* __restrict__ C, __half* __restrict__ Ch,
    int ldc, const float* __restrict__ bias,
    int M, int N, int K, int flags)
{
    extern __shared__ __half smbuf[];
    int tid = threadIdx.x;
    int m0 = blockIdx.y * BM;
    int n0 = blockIdx.x * BN;
    // split-K: z-slice shifts operands; C goes to partial buffer slice kz
    int kz = blockIdx.z;
    if (kz) {
        A += (size_t)kz * K;
        B += (size_t)kz * K * (size_t)ldb;
        C += (size_t)kz * (size_t)M * (size_t)ldc;
    }
    int warp = tid >> 5;
    int lane = tid & 31;
    int wm = (warp >> 2) * 64;
    int wn = (warp & 3) * 32;

    float acc[4][4][4];
    #pragma unroll
    for (int i = 0; i < 4; i++)
        #pragma unroll
        for (int j = 0; j < 4; j++)
            #pragma unroll
            for (int c = 0; c < 4; c++) acc[i][j][c] = 0.f;

    uint32_t smem_u32 = (uint32_t)__cvta_generic_to_shared(smbuf);
    const int nk = K / BKK;

    gemm_issue_stage(smem_u32, 0, A, lda, B, ldb, M, m0, n0, 0, tid);
    cp_commit();
    gemm_issue_stage(smem_u32, 1, A, lda, B, ldb, M, m0, n0, BKK, tid);
    cp_commit();

    int st = 0;
    for (int kt = 0; kt < nk; kt++) {
        cp_wait1();
        __syncthreads();

        int nxt = kt + 2;
        if (nxt < nk) {
            int nst = st + 2;
            if (nst >= NSTAGE) nst -= NSTAGE;
            gemm_issue_stage(smem_u32, nst, A, lda, B, ldb, M, m0, n0, nxt * BKK, tid);
        }
        cp_commit();

        uint32_t s = smem_u32 + (uint32_t)st * STAGE_BYTES;
        uint32_t a_base = s;
        uint32_t b_base = s + ASZ * 2;

        #pragma unroll
        for (int ks = 0; ks < 2; ks++) {
            int kc = ks * 16;
            uint32_t bf[4][2];
            int brow = kc + ((lane >> 3) & 1) * 8 + (lane & 7);
            #pragma unroll
            for (int j = 0; j < 2; j++) {
                int bcol = wn + j * 16 + (lane >> 4) * 8;
                uint32_t off = (uint32_t)((brow * BSTR + bcol) * 2);
                uint32_t th[4];
                ldsm_x4_t(b_base + off, th);
                bf[2 * j][0] = th[0];
                bf[2 * j][1] = th[1];
                bf[2 * j + 1][0] = th[2];
                bf[2 * j + 1][1] = th[3];
            }
            int arow = lane & 15;
            int acol = kc + (lane >> 4) * 8;
            #pragma unroll
            for (int mi = 0; mi < 4; mi++) {
                uint32_t af[4];
                uint32_t off = (uint32_t)(((wm + mi * 16 + arow) * ASTR + acol) * 2);
                ldsm_x4(a_base + off, af);
                #pragma unroll
                for (int ni = 0; ni < 4; ni++) {
                    mma_f16(acc[mi][ni], af, bf[ni]);
                }
            }
        }

        st = (st + 1 == NSTAGE) ? 0 : st + 1;
    }

    // ---- epilogue ----
    #pragma unroll
    for (int mi = 0; mi < 4; mi++) {
        int r0 = m0 + wm + mi * 16 + (lane >> 2);
        #pragma unroll
        for (int ni = 0; ni < 4; ni++) {
            int c0 = n0 + wn + ni * 8 + (lane & 3) * 2;
            #pragma unroll
            for (int half = 0; half < 2; half++) {
                int r = r0 + half * 8;
                if (r >= M) continue;
                #pragma unroll
                for (int e = 0; e < 2; e++) {
                    int c = c0 + e;
                    float val = acc[mi][ni][half * 2 + e];
                    if (flags & FLAG_BIAS) val += bias[c];
                    if (flags & FLAG_GELU) val = gelu_exact(val);
                    if (flags & FLAG_HALF_OUT) {
                        Ch[(size_t)r * ldc + c] = __float2half(val);
                    } else {
                        float* p = &C[(size_t)r * ldc + c];
                        if (flags & FLAG_RES) *p += val; else *p = val;
                    }
                }
            }
        }
    }
}

// ---------------- split-K reduce for MLP2: x += p0 + p1 + b2 ----------------
__global__ __launch_bounds__(256) void mlp2_reduce(const float* __restrict__ part,
                                                   const float* __restrict__ b2,
                                                   float* __restrict__ x) {
    int i = (blockIdx.x * blockDim.x + threadIdx.x) * 4;
    if (i >= ROWS * DD) return;
    int col = i % DD;
    float4 a = *(const float4*)&part[i];
    float4 b = *(const float4*)&part[ROWS * DD + i];
    float4 bi = *(const float4*)&b2[col];
    float4 xv = *(float4*)&x[i];
    xv.x += a.x + b.x + bi.x;
    xv.y += a.y + b.y + bi.y;
    xv.z += a.z + b.z + bi.z;
    xv.w += a.w + b.w + bi.w;
    *(float4*)&x[i] = xv;
}

// ================= fused QKV + attention: block per (n, head), 13 warps ==========
#define AT_ROWS 208
#define AT_STR 72
#define HS_ELEMS (AT_ROWS * AT_STR)          // 14976
#define WS_ELEMS (3 * 64 * AT_STR)           // 13824
#define FUSED_SMEM_BYTES ((2 * HS_ELEMS + WS_ELEMS + HS_ELEMS) * 2)   // 117504
#define FW_THREADS 416

__global__ __launch_bounds__(FW_THREADS, 1) void qkv_attn_fused(
    const __half* __restrict__ hbuf,
    const float* __restrict__ Wq, const float* __restrict__ Wk, const float* __restrict__ Wv,
    const float* __restrict__ bq, const float* __restrict__ bk, const float* __restrict__ bv,
    float* __restrict__ x)
{
    extern __shared__ __half fsm[];
    __half* Hs = fsm;
    __half* Ws = Hs + HS_ELEMS;
    __half* Ks = Ws + WS_ELEMS;
    __half* Vs = Ks + HS_ELEMS;

    int nh = blockIdx.x;
    int n = nh / HH, h = nh - n * HH;
    int tid = threadIdx.x;
    int warp = tid >> 5, lane = tid & 31;

    #pragma unroll
    for (int i = 0; i < 4; i++) {
        int idx = tid + i * FW_THREADS;
        int t = idx >> 3;
        int c8 = (idx & 7) * 8;
        uint4 hv = make_uint4(0, 0, 0, 0);
        if (t < SS) hv = *(const uint4*)(hbuf + ((size_t)(n * SS + t)) * DD + h * DH + c8);
        *(uint4*)(Hs + t * AT_STR + c8) = hv;
    }
    const float* wsrc[3] = {Wq + h * DH * DH, Wk + h * DH * DH, Wv + h * DH * DH};
    for (int idx = tid; idx < 3 * DH * DH; idx += FW_THREADS) {
        int mat = idx >> 12;
        int rem = idx & 4095;
        int d = rem >> 6, e = rem & 63;
        Ws[mat * 64 * AT_STR + d * AT_STR + e] = __float2half(wsrc[mat][d * 64 + e]);
    }
    __syncthreads();

    uint32_t h_base = (uint32_t)__cvta_generic_to_shared(Hs);
    uint32_t w_base = (uint32_t)__cvta_generic_to_shared(Ws);
    uint32_t k_base = (uint32_t)__cvta_generic_to_shared(Ks);
    uint32_t v_base = (uint32_t)__cvta_generic_to_shared(Vs);

    int s0 = warp * 16;

    float acc[3][8][4];
    #pragma unroll
    for (int m = 0; m < 3; m++)
        #pragma unroll
        for (int j = 0; j < 8; j++) {
            acc[m][j][0] = 0.f; acc[m][j][1] = 0.f;
            acc[m][j][2] = 0.f; acc[m][j][3] = 0.f;
        }

    #pragma unroll
    for (int ks = 0; ks < 4; ks++) {
        int kc = ks * 16;
        uint32_t af[4];
        uint32_t aoff = (uint32_t)(((s0 + (lane & 15)) * AT_STR + kc + (lane >> 4) * 8) * 2);
        ldsm_x4(h_base + aoff, af);
        int brow = kc + ((lane >> 3) & 1) * 8 + (lane & 7);
        #pragma unroll
        for (int mat = 0; mat < 3; mat++) {
            #pragma unroll
            for (int j = 0; j < 4; j++) {
                int bcol = j * 16 + (lane >> 4) * 8;
                uint32_t th[4];
                ldsm_x4_t(w_base + (uint32_t)((mat * 64 * AT_STR + brow * AT_STR + bcol) * 2), th);
                mma_f16(acc[mat][2 * j],     af, th);
                mma_f16(acc[mat][2 * j + 1], af, th + 2);
            }
        }
    }

    const float* bq_h = bq + h * DH;
    uint32_t qa[4][4];
    #pragma unroll
    for (int ks = 0; ks < 4; ks++) {
        int colA = 16 * ks + (lane & 3) * 2;
        int colB = colA + 8;
        float b0 = bq_h[colA], b1 = bq_h[colA + 1];
        float b2 = bq_h[colB], b3 = bq_h[colB + 1];
        __half2 t0 = __floats2half2_rn(acc[0][2 * ks][0] + b0, acc[0][2 * ks][1] + b1);
        __half2 t1 = __floats2half2_rn(acc[0][2 * ks][2] + b0, acc[0][2 * ks][3] + b1);
        __half2 t2 = __floats2half2_rn(acc[0][2 * ks + 1][0] + b2, acc[0][2 * ks + 1][1] + b3);
        __half2 t3 = __floats2half2_rn(acc[0][2 * ks + 1][2] + b2, acc[0][2 * ks + 1][3] + b3);
        qa[ks][0] = *(uint32_t*)&t0;
        qa[ks][1] = *(uint32_t*)&t1;
        qa[ks][2] = *(uint32_t*)&t2;
        qa[ks][3] = *(uint32_t*)&t3;
    }

    {
        const float* bk_h = bk + h * DH;
        const float* bv_h = bv + h * DH;
        #pragma unroll
        for (int half = 0; half < 2; half++) {
            int r = s0 + (lane >> 2) + half * 8;
            __half* krow = Ks + r * AT_STR;
            __half* vrow = Vs + r * AT_STR;
            #pragma unroll
            for (int nj = 0; nj < 8; nj++) {
                int col = nj * 8 + (lane & 3) * 2;
                __half2 kv = __floats2half2_rn(acc[1][nj][half * 2]     + bk_h[col],
                                               acc[1][nj][half * 2 + 1] + bk_h[col + 1]);
                __half2 vv = __floats2half2_rn(acc[2][nj][half * 2]     + bv_h[col],
                                               acc[2][nj][half * 2 + 1] + bv_h[col + 1]);
                *(__half2*)&krow[col] = kv;
                *(__half2*)&vrow[col] = vv;
            }
        }
    }
    __syncthreads();

    const float scale = 0.125f;
    float c[26][4];
    #pragma unroll
    for (int j = 0; j < 26; j++) {
        c[j][0] = 0.f; c[j][1] = 0.f; c[j][2] = 0.f; c[j][3] = 0.f;
    }
    #pragma unroll
    for (int ks = 0; ks < 4; ks++) {
        int ncol = ks * 16 + ((lane >> 3) & 1) * 8;
        #pragma unroll
        for (int j = 0; j < 13; j++) {
            uint32_t b[4];
            int nrow = j * 16 + (lane >> 4) * 8 + (lane & 7);
            ldsm_x4(k_base + (uint32_t)((nrow * AT_STR + ncol) * 2), b);
            mma_f16(c[2 * j],     qa[ks], b);
            mma_f16(c[2 * j + 1], qa[ks], b + 2);
        }
    }

    float mx0 = -1e30f, mx1 = -1e30f;
    #pragma unroll
    for (int j = 0; j < 26; j++) {
        int tcol = j * 8 + (lane & 3) * 2;
        #pragma unroll
        for (int e = 0; e < 2; e++) {
            float s0v = c[j][e] * scale;
            float s1v = c[j][2 + e] * scale;
            if (tcol + e >= SS) { s0v = -1e30f; s1v = -1e30f; }
            c[j][e] = s0v;
            c[j][2 + e] = s1v;
            mx0 = fmaxf(mx0, s0v);
            mx1 = fmaxf(mx1, s1v);
        }
    }
    mx0 = fmaxf(mx0, __shfl_xor_sync(0xffffffffu, mx0, 1));
    mx0 = fmaxf(mx0, __shfl_xor_sync(0xffffffffu, mx0, 2));
    mx1 = fmaxf(mx1, __shfl_xor_sync(0xffffffffu, mx1, 1));
    mx1 = fmaxf(mx1, __shfl_xor_sync(0xffffffffu, mx1, 2));

    float sum0 = 0.f, sum1 = 0.f;
    #pragma unroll
    for (int j = 0; j < 26; j++) {
        #pragma unroll
        for (int e = 0; e < 2; e++) {
            float p0 = __expf(c[j][e] - mx0);
            float p1 = __expf(c[j][2 + e] - mx1);
            c[j][e] = p0;
            c[j][2 + e] = p1;
            sum0 += p0;
            sum1 += p1;
        }
    }
    sum0 += __shfl_xor_sync(0xffffffffu, sum0, 1);
    sum0 += __shfl_xor_sync(0xffffffffu, sum0, 2);
    sum1 += __shfl_xor_sync(0xffffffffu, sum1, 1);
    sum1 += __shfl_xor_sync(0xffffffffu, sum1, 2);
    float inv0 = 1.0f / sum0;
    float inv1 = 1.0f / sum1;

    float o[8][4];
    #pragma unroll
    for (int j = 0; j < 8; j++) {
        o[j][0] = 0.f; o[j][1] = 0.f; o[j][2] = 0.f; o[j][3] = 0.f;
    }
    #pragma unroll
    for (int j = 0; j < 13; j++) {
        uint32_t a[4];
        __half2 h0 = __floats2half2_rn(c[2 * j][0] * inv0, c[2 * j][1] * inv0);
        __half2 h1 = __floats2half2_rn(c[2 * j][2] * inv1, c[2 * j][3] * inv1);
        __half2 h2 = __floats2half2_rn(c[2 * j + 1][0] * inv0, c[2 * j + 1][1] * inv0);
        __half2 h3 = __floats2half2_rn(c[2 * j + 1][2] * inv1, c[2 * j + 1][3] * inv1);
        a[0] = *(uint32_t*)&h0;
        a[1] = *(uint32_t*)&h1;
        a[2] = *(uint32_t*)&h2;
        a[3] = *(uint32_t*)&h3;
        int brow = j * 16 + ((lane >> 3) & 1) * 8 + (lane & 7);
        #pragma unroll
        for (int nj = 0; nj < 4; nj++) {
            uint32_t b[4];
            int bcol = nj * 16 + (lane >> 4) * 8;
            ldsm_x4_t(v_base + (uint32_t)((brow * AT_STR + bcol) * 2), b);
            mma_f16(o[2 * nj],     a, b);
            mma_f16(o[2 * nj + 1], a, b + 2);
        }
    }

    int rloc = lane >> 2;
    #pragma unroll
    for (int half = 0; half < 2; half++) {
        int srow = s0 + rloc + half * 8;
        if (srow >= SS) continue;
        float* xr = x + ((size_t)(n * SS + srow)) * DD + h * DH;
        #pragma unroll
        for (int nj = 0; nj < 8; nj++) {
            int col = nj * 8 + (lane & 3) * 2;
            xr[col]     += o[nj][half * 2];
            xr[col + 1] += o[nj][half * 2 + 1];
        }
    }
}

// ---------------- split-K classification head: grid (16 n-tiles, 4 k-chunks) -------
__global__ __launch_bounds__(256) void head_gemm(const float* __restrict__ x,
                                                 const float* __restrict__ Wout,
                                                 float* __restrict__ part) {
    __shared__ float As[16][34];
    __shared__ float Bs[16][68];
    int tid = threadIdx.x;
    int n0 = blockIdx.x * 64;
    int kz = blockIdx.y;
    int tx = tid & 15, ty = tid >> 4;

    float acc[2][4];
    acc[0][0] = 0.f; acc[0][1] = 0.f; acc[0][2] = 0.f; acc[0][3] = 0.f;
    acc[1][0] = 0.f; acc[1][1] = 0.f; acc[1][2] = 0.f; acc[1][3] = 0.f;

    for (int k0 = kz * 192; k0 < kz * 192 + 192; k0 += 16) {
        if (tid < 128) {
            int arow = tid >> 2;
            int akcol = (tid & 3) * 4;
            float4 a4 = *(const float4*)&x[(size_t)arow * (SS * DD) + k0 + akcol];
            As[akcol + 0][arow] = a4.x;
            As[akcol + 1][arow] = a4.y;
            As[akcol + 2][arow] = a4.z;
            As[akcol + 3][arow] = a4.w;
        }
        {
            int brow = tid >> 4;
            int bcol = (tid & 15) * 4;
            int gn = n0 + bcol;
            const float* Brow = &Wout[(size_t)(k0 + brow) * OUTC];
            float4 b4;
            b4.x = (gn + 0 < OUTC) ? Brow[gn + 0] : 0.f;
            b4.y = (gn + 1 < OUTC) ? Brow[gn + 1] : 0.f;
            b4.z = (gn + 2 < OUTC) ? Brow[gn + 2] : 0.f;
            b4.w = (gn + 3 < OUTC) ? Brow[gn + 3] : 0.f;
            *(float4*)&Bs[brow][bcol] = b4;
        }
        __syncthreads();

        #pragma unroll
        for (int kk = 0; kk < 16; kk++) {
            float a0 = As[kk][ty * 2];
            float a1 = As[kk][ty * 2 + 1];
            float4 b4 = *(float4*)&Bs[kk][tx * 4];
            acc[0][0] += a0 * b4.x; acc[0][1] += a0 * b4.y;
            acc[0][2] += a0 * b4.z; acc[0][3] += a0 * b4.w;
            acc[1][0] += a1 * b4.x; acc[1][1] += a1 * b4.y;
            acc[1][2] += a1 * b4.z; acc[1][3] += a1 * b4.w;
        }
        __syncthreads();
    }

    float* pbase = part + (size_t)kz * NN * OUTC;
    #pragma unroll
    for (int i = 0; i < 2; i++) {
        int r = ty * 2 + i;
        #pragma unroll
        for (int j = 0; j < 4; j++) {
            int cidx = n0 + tx * 4 + j;
            if (cidx < OUTC) pbase[(size_t)r * OUTC + cidx] = acc[i][j];
        }
    }
}

// ---------------- final softmax (sums 4 K-partials + bias) ----------------
__global__ __launch_bounds__(256) void softmax_out(const float* __restrict__ part,
                                                   const float* __restrict__ bout,
                                                   float* __restrict__ out) {
    __shared__ float sl[OUTC];
    __shared__ float sh[8];
    int n = blockIdx.x;
    int tid = threadIdx.x;
    int lane = tid & 31, wp = tid >> 5;

    for (int cidx = tid; cidx < OUTC; cidx += 256) {
        size_t o = (size_t)n * OUTC + cidx;
        sl[cidx] = bout[cidx] + part[o] + part[NN * OUTC + o] +
                   part[2 * NN * OUTC + o] + part[3 * NN * OUTC + o];
    }
    __syncthreads();

    float mx = -1e30f;
    for (int cidx = tid; cidx < OUTC; cidx += 256) mx = fmaxf(mx, sl[cidx]);
    #pragma unroll
    for (int o = 16; o; o >>= 1) mx = fmaxf(mx, __shfl_xor_sync(0xffffffffu, mx, o));
    if (lane == 0) sh[wp] = mx;
    __syncthreads();
    float gmx = sh[0];
    #pragma unroll
    for (int i = 1; i < 8; i++) gmx = fmaxf(gmx, sh[i]);
    __syncthreads();

    float sum = 0.f;
    for (int cidx = tid; cidx < OUTC; cidx += 256) sum += __expf(sl[cidx] - gmx);
    #pragma unroll
    for (int o = 16; o; o >>= 1) sum += __shfl_xor_sync(0xffffffffu, sum, o);
    if (lane == 0) sh[wp] = sum;
    __syncthreads();
    float tot = 0.f;
    #pragma unroll
    for (int i = 0; i < 8; i++) tot += sh[i];
    float inv = 1.0f / tot;

    for (int cidx = tid; cidx < OUTC; cidx += 256)
        out[(size_t)n * OUTC + cidx] = __expf(sl[cidx] - gmx) * inv;
}

// ---------------- launch ----------------
extern "C" void kernel_launch(void* const* d_in, const int* in_sizes, int n_in,
                              void* d_out, int out_size) {
    const float* images = (const float*)d_in[0];
    const float* Wm     = (const float*)d_in[1];
    const float* bm     = (const float*)d_in[2];
    const float* cls    = (const float*)d_in[3];
    const float* pos    = (const float*)d_in[4];
    const float* ln1w   = (const float*)d_in[5];
    const float* ln1b   = (const float*)d_in[6];
    const float* Wq     = (const float*)d_in[7];
    const float* bq     = (const float*)d_in[8];
    const float* Wk     = (const float*)d_in[9];
    const float* bk     = (const float*)d_in[10];
    const float* Wv     = (const float*)d_in[11];
    const float* bv     = (const float*)d_in[12];
    const float* ln2w   = (const float*)d_in[13];
    const float* ln2b   = (const float*)d_in[14];
    const float* W1     = (const float*)d_in[15];
    const float* b1     = (const float*)d_in[16];
    const float* W2     = (const float*)d_in[17];
    const float* b2     = (const float*)d_in[18];
    const float* Wout   = (const float*)d_in[19];
    const float* bout   = (const float*)d_in[20];
    float* out = (float*)d_out;

    float *p_x, *p_scr, *p_lpart;
    cudaGetSymbolAddress((void**)&p_x, g_x);
    cudaGetSymbolAddress((void**)&p_scr, g_scratch);
    cudaGetSymbolAddress((void**)&p_lpart, g_lpart);

    __half *p_patch, *p_hh, *p_u, *p_Wm, *p_W1, *p_W2;
    cudaGetSymbolAddress((void**)&p_patch, g_patch_f16);
    cudaGetSymbolAddress((void**)&p_hh, g_h_f16);
    cudaGetSymbolAddress((void**)&p_u, g_u_f16);
    cudaGetSymbolAddress((void**)&p_Wm, g_Wm_f16);
    cudaGetSymbolAddress((void**)&p_W1, g_W1_f16);
    cudaGetSymbolAddress((void**)&p_W2, g_W2_f16);

    cudaFuncSetAttribute(qkv_attn_fused, cudaFuncAttributeMaxDynamicSharedMemorySize, FUSED_SMEM_BYTES);
    cudaFuncSetAttribute(gemm_f16, cudaFuncAttributeMaxDynamicSharedMemorySize, GEMM_SMEM_BYTES);

    // ---- one-time weight conversions ----
    conv_f16<<<(DD * DD / 4 + 255) / 256, 256>>>(Wm, p_Wm, DD * DD);
    conv_f16<<<(LL * DD * FF / 4 + 255) / 256, 256>>>(W1, p_W1, LL * DD * FF);
    conv_f16<<<(LL * FF * DD / 4 + 255) / 256, 256>>>(W2, p_W2, LL * FF * DD);

    // ---- patch extraction + embed GEMM (294 blocks: single wave) ----
    extract_patches<<<(PROWS * DD + 255) / 256, 256>>>(images, p_patch);
    gemm_f16<<<dim3(DD / 128, (PROWS + 127) / 128), 256, GEMM_SMEM_BYTES>>>(
        p_patch, DD, p_Wm, DD,
        p_scr, nullptr, DD, bm, PROWS, DD, DD, FLAG_BIAS);
    assemble<<<(ROWS * DD + 255) / 256, 256>>>(p_scr, cls, pos, p_x);

    for (int l = 0; l < LL; l++) {
        ln_warp<<<ROWS / 8, 256>>>(p_x, ln1w + l * DD, ln1b + l * DD, p_hh);

        qkv_attn_fused<<<NN * HH, FW_THREADS, FUSED_SMEM_BYTES>>>(
            p_hh,
            Wq + (size_t)l * HH * DH * DH, Wk + (size_t)l * HH * DH * DH, Wv + (size_t)l * HH * DH * DH,
            bq + (size_t)l * DD, bk + (size_t)l * DD, bv + (size_t)l * DD,
            p_x);

        ln_warp<<<ROWS / 8, 256>>>(p_x, ln2w + l * DD, ln2b + l * DD, p_hh);

        // MLP1: 24x50 = 1200 blocks (4.05 waves, ~1% tail)
        gemm_f16<<<dim3(FF / 128, (ROWS + 127) / 128), 256, GEMM_SMEM_BYTES>>>(
            p_hh, DD,
            p_W1 + (size_t)l * DD * FF, FF,
            nullptr, p_u, FF, b1 + (size_t)l * FF,
            ROWS, FF, DD, FLAG_BIAS | FLAG_GELU | FLAG_HALF_OUT);

        // MLP2: split-K 2 with full 128x128 tiles -> 600 blocks (2.03 waves)
        gemm_f16<<<dim3(DD / 128, (ROWS + 127) / 128, 2), 256, GEMM_SMEM_BYTES>>>(
            p_u, FF,
            p_W2 + (size_t)l * FF * DD, DD,
            p_scr, nullptr, DD, nullptr,
            ROWS, DD, FF / 2, 0);
        mlp2_reduce<<<(ROWS * DD / 4 + 255) / 256, 256>>>(p_scr, b2 + (size_t)l * DD, p_x);
    }

    // classification head: split-K partials (deterministic), bias+reduce in softmax
    head_gemm<<<dim3(16, 4), 256>>>(p_x, Wout, p_lpart);
    softmax_out<<<NN, 256>>>(p_lpart, bout, out);
}